// round 13
// baseline (speedup 1.0000x reference)
#include <cuda_runtime.h>
#include <cuda_bf16.h>
#include <math.h>
#include <float.h>

#define BATCH 8
#define NPT   2048
#define M1C   1024
#define M2C   256
#define KNB   64
#define CURVK 10

// ---- scratch (device globals; no allocation) ----
__device__ float g_curv [BATCH*NPT];
__device__ float g_pos1 [BATCH*M1C*3];
__device__ float g_curv1[BATCH*M1C];
__device__ float g_pos2 [BATCH*M2C*3];
__device__ int   g_nidx1[BATCH*M1C*KNB];
__device__ int   g_cnt1 [BATCH*M1C];
__device__ int   g_nidx2[BATCH*M2C*KNB];
__device__ int   g_cnt2 [BATCH*M2C];
__device__ float g_x1   [BATCH*M1C*128];
__device__ float g_x2   [BATCH*M2C*256];
__device__ float g_gfeat[BATCH*1024];
__device__ float g_featF[1024*1024];          // y1 (8192x128)
__device__ float g_bufA [2*1024*1024];        // SA3 final fp32 (2048x1024)
__device__ __nv_bfloat16 g_w1bh[4096],  g_w1bl[4096];
__device__ __nv_bfloat16 g_w1ch[8192],  g_w1cl[8192];
__device__ __nv_bfloat16 g_w2bh[16384], g_w2bl[16384];
__device__ __nv_bfloat16 g_w2ch[32768], g_w2cl[32768];
__device__ __nv_bfloat16 g_w3ah[73728], g_w3al[73728];
__device__ __nv_bfloat16 g_w3bh[131072],g_w3bl[131072];
__device__ __nv_bfloat16 g_w3ch[524288],g_w3cl[524288];
__device__ __nv_bfloat16 g_pAh[589824], g_pAl[589824];
__device__ __nv_bfloat16 g_pBh[524288], g_pBl[524288];
__device__ __nv_bfloat16 g_pCh[1048576],g_pCl[1048576];

__device__ __forceinline__ void splitf(float v, __nv_bfloat16& h, __nv_bfloat16& l) {
    h = __float2bfloat16(v);
    l = __float2bfloat16(v - __bfloat162float(h));
}

__device__ __forceinline__ void mma16816(float* c, const unsigned* a, const unsigned* b) {
    asm volatile(
      "mma.sync.aligned.m16n8k16.row.col.f32.bf16.bf16.f32 "
      "{%0,%1,%2,%3}, {%4,%5,%6,%7}, {%8,%9}, {%0,%1,%2,%3};\n"
      : "+f"(c[0]), "+f"(c[1]), "+f"(c[2]), "+f"(c[3])
      : "r"(a[0]), "r"(a[1]), "r"(a[2]), "r"(a[3]), "r"(b[0]), "r"(b[1]));
}

template<int NF,int K16,int S>
__device__ __forceinline__ void mma_block(
    float (&acc)[2][8][4],
    const __nv_bfloat16* AsH, const __nv_bfloat16* AsL,
    const __nv_bfloat16* WH,  const __nv_bfloat16* WL,
    int wm, int wnbase, int lane)
{
#pragma unroll
    for (int k16=0;k16<K16;++k16){
        const int kk=k16*16+(lane&3)*2;
        unsigned ah[2][4], al[2][4];
#pragma unroll
        for (int mf=0;mf<2;++mf){
            int r=wm*32+mf*16+(lane>>2);
            ah[mf][0]=*(const unsigned*)&AsH[r*S+kk];
            ah[mf][1]=*(const unsigned*)&AsH[(r+8)*S+kk];
            ah[mf][2]=*(const unsigned*)&AsH[r*S+kk+8];
            ah[mf][3]=*(const unsigned*)&AsH[(r+8)*S+kk+8];
            al[mf][0]=*(const unsigned*)&AsL[r*S+kk];
            al[mf][1]=*(const unsigned*)&AsL[(r+8)*S+kk];
            al[mf][2]=*(const unsigned*)&AsL[r*S+kk+8];
            al[mf][3]=*(const unsigned*)&AsL[(r+8)*S+kk+8];
        }
#pragma unroll
        for (int nf=0;nf<NF;++nf){
            int n=wnbase+nf*8+(lane>>2);
            unsigned bh[2]={*(const unsigned*)&WH[n*S+kk], *(const unsigned*)&WH[n*S+kk+8]};
            unsigned bl[2]={*(const unsigned*)&WL[n*S+kk], *(const unsigned*)&WL[n*S+kk+8]};
#pragma unroll
            for (int mf=0;mf<2;++mf){
                mma16816(acc[mf][nf], ah[mf], bh);
                mma16816(acc[mf][nf], ah[mf], bl);
                mma16816(acc[mf][nf], al[mf], bh);
            }
        }
    }
}

// ---- curvature ----
__global__ void curvature_kernel(const float* __restrict__ pos, float* __restrict__ curv)
{
    __shared__ float px[NPT], py[NPT], pz[NPT], nr[NPT];
    const int b = blockIdx.x / (NPT/128);
    const int tid = threadIdx.x;
    const float* cp = pos + (size_t)b * NPT * 3;
    for (int i = tid; i < NPT; i += 128) {
        float x = cp[3*i], y = cp[3*i+1], z = cp[3*i+2];
        px[i]=x; py[i]=y; pz[i]=z; nr[i]=x*x+y*y+z*z;
    }
    __syncthreads();
    const int i = (blockIdx.x % (NPT/128)) * 128 + tid;
    const float qx=px[i], qy=py[i], qz=pz[i], nq=nr[i];

    float td[CURVK]; int ti[CURVK];
#pragma unroll
    for (int s = 0; s < CURVK; ++s) { td[s]=3.4e38f; ti[s]=0; }
    for (int j = 0; j < NPT; ++j) {
        float d2 = nq + nr[j] - 2.0f*(qx*px[j]+qy*py[j]+qz*pz[j]);
        if (d2 < td[CURVK-1]) {
            float cd=d2; int ci=j;
#pragma unroll
            for (int s = 0; s < CURVK; ++s)
                if (cd < td[s]) { float t=td[s]; td[s]=cd; cd=t; int u=ti[s]; ti[s]=ci; ci=u; }
        }
    }
    float mx=0,my=0,mz=0;
#pragma unroll
    for (int s = 0; s < CURVK; ++s) { mx+=px[ti[s]]; my+=py[ti[s]]; mz+=pz[ti[s]]; }
    mx/=CURVK; my/=CURVK; mz/=CURVK;
    double cxx=0,cxy=0,cxz=0,cyy=0,cyz=0,czz=0;
#pragma unroll
    for (int s = 0; s < CURVK; ++s) {
        float ax=px[ti[s]]-mx, ay=py[ti[s]]-my, az=pz[ti[s]]-mz;
        cxx+=(double)ax*ax; cxy+=(double)ax*ay; cxz+=(double)ax*az;
        cyy+=(double)ay*ay; cyz+=(double)ay*az; czz+=(double)az*az;
    }
    cxx/=CURVK; cxy/=CURVK; cxz/=CURVK; cyy/=CURVK; cyz/=CURVK; czz/=CURVK;
    double tr=cxx+cyy+czz;
    double p1=cxy*cxy+cxz*cxz+cyz*cyz;
    double q=tr/3.0;
    double p2=(cxx-q)*(cxx-q)+(cyy-q)*(cyy-q)+(czz-q)*(czz-q)+2.0*p1;
    double lmin;
    if (p2 < 1e-32) lmin = q;
    else {
        double p=sqrt(p2/6.0);
        double b00=(cxx-q)/p,b11=(cyy-q)/p,b22=(czz-q)/p,b01=cxy/p,b02=cxz/p,b12=cyz/p;
        double detB=b00*(b11*b22-b12*b12)-b01*(b01*b22-b12*b02)+b02*(b01*b12-b11*b02);
        double r=fmin(1.0,fmax(-1.0,detB*0.5));
        lmin=q+2.0*p*cos(acos(r)/3.0 + 2.0943951023931953);
    }
    curv[b*NPT+i]=(float)(lmin/(tr+1e-8));
}

__global__ void dummy_kernel() {}

// ---- weighted FPS with fused gather (R8 body, 256 thr) ----
template<int NPTS,int MOUT>
__global__ void __launch_bounds__(256) fps_kernel(const float* __restrict__ pos,
                                                  const float* __restrict__ curv,
                                                  float* __restrict__ opos,
                                                  float* __restrict__ ocurv)
{
    constexpr int THR=256, E=NPTS/THR, NW=8;
    __shared__ float spx[NPTS], spy[NPTS], spz[NPTS], scv[NPTS];
    __shared__ unsigned long long wkey[2][NW];
    const int b=blockIdx.x, tid=threadIdx.x, lane=tid&31, wid=tid>>5;
    const float* cp = pos + (size_t)b*NPTS*3;
    float px[E],py[E],pz[E],ww[E],md[E];
#pragma unroll
    for (int e=0;e<E;++e){
        int i=tid+e*THR;
        float x=cp[3*i], y=cp[3*i+1], z=cp[3*i+2];
        float cv=curv[b*NPTS+i];
        px[e]=x; py[e]=y; pz[e]=z;
        spx[i]=x; spy[i]=y; spz[i]=z; scv[i]=cv;
        ww[e]=1.0f+10.0f*cv;
        md[e]=FLT_MAX;
    }
    __syncthreads();
    float sx=spx[0], sy=spy[0], sz=spz[0];
    if (tid==0){
        int o=b*MOUT;
        opos[3*o]=sx; opos[3*o+1]=sy; opos[3*o+2]=sz;
        if (ocurv) ocurv[o]=scv[0];
    }
    for (int m=1;m<MOUT;++m){
        float bv=-1.f; int bi=0;
#pragma unroll
        for (int e=0;e<E;++e){
            int i=tid+e*THR;
            float dx=px[e]-sx, dy=py[e]-sy, dz=pz[e]-sz;
            float d=fminf(md[e], dx*dx+dy*dy+dz*dz);
            md[e]=d;
            float v=d*ww[e];
            if (v>bv){ bv=v; bi=i; }   // i increasing per thread -> first max kept
        }
        unsigned hv=__float_as_uint(bv);
        unsigned hm=__reduce_max_sync(0xffffffffu, hv);
        unsigned lm=__reduce_max_sync(0xffffffffu, (hv==hm)? ~(unsigned)bi : 0u);
        if (lane==0) wkey[m&1][wid]=((unsigned long long)hm<<32)|lm;
        __syncthreads();
        unsigned long long k2 = (lane<NW)? wkey[m&1][lane] : 0ull;
        unsigned h2=(unsigned)(k2>>32), l2=(unsigned)k2;
        unsigned hm2=__reduce_max_sync(0xffffffffu, h2);
        unsigned lm2=__reduce_max_sync(0xffffffffu, (h2==hm2)? l2 : 0u);
        int s=(int)(~lm2);
        sx=spx[s]; sy=spy[s]; sz=spz[s];
        if (tid==0){
            int o=b*MOUT+m;
            opos[3*o]=sx; opos[3*o+1]=sy; opos[3*o+2]=sz;
            if (ocurv) ocurv[o]=scv[s];
        }
    }
}

// ---- radius grouping (R8 config) ----
template<int NPTS,int CAP,int CPB>
__global__ void group_kernel(const float* __restrict__ pts, const float* __restrict__ cents,
                             int* __restrict__ nidx, int* __restrict__ cnt_out,
                             int MC, float r2)
{
    __shared__ float px[NPTS],py[NPTS],pz[NPTS],nr[NPTS];
    __shared__ unsigned long long cand[CPB][CAP];
    const int b=blockIdx.y, tid=threadIdx.x;
    const float* cp = pts + (size_t)b*NPTS*3;
    for (int i = tid; i < NPTS; i += CPB*32) {
        float x=cp[3*i],y=cp[3*i+1],z=cp[3*i+2];
        px[i]=x; py[i]=y; pz[i]=z; nr[i]=x*x+y*y+z*z;
    }
    __syncthreads();
    const int w=tid>>5, lane=tid&31;
    const int c=blockIdx.x*CPB+w, cg=b*MC+c;
    const float cx=cents[3*cg],cy=cents[3*cg+1],cz=cents[3*cg+2];
    const float nc=cx*cx+cy*cy+cz*cz;
    int cnt=0;
    for (int j0 = 0; j0 < NPTS; j0 += 32) {
        int j=j0+lane;
        float d2 = nc + nr[j] - 2.0f*(cx*px[j]+cy*py[j]+cz*pz[j]);
        bool in = (d2 <= r2);
        unsigned mask = __ballot_sync(0xffffffffu, in);
        if (in) {
            int p = cnt + __popc(mask & ((1u<<lane)-1u));
            if (p < CAP) {
                unsigned ub=__float_as_uint(d2);
                ub = (ub&0x80000000u) ? ~ub : (ub|0x80000000u);
                cand[w][p] = ((unsigned long long)ub<<32) | (unsigned)j;
            }
        }
        cnt += __popc(mask);
    }
    if (cnt > CAP) cnt = CAP;
    for (int i = cnt+lane; i < CAP; i += 32) cand[w][i]=0xFFFFFFFFFFFFFFFFull;
    __syncwarp();
    for (int k = 2; k <= CAP; k <<= 1)
        for (int j = k>>1; j > 0; j >>= 1) {
            for (int i = lane; i < CAP; i += 32) {
                int ixj = i^j;
                if (ixj > i) {
                    unsigned long long a=cand[w][i], bb=cand[w][ixj];
                    if ((a>bb) == ((i&k)==0)) { cand[w][i]=bb; cand[w][ixj]=a; }
                }
            }
            __syncwarp();
        }
    int nv = cnt < KNB ? cnt : KNB;
    int fb = (nv>0) ? (int)(cand[w][0]&0xffffffffu) : 0;
    for (int i = lane; i < KNB; i += 32)
        nidx[(size_t)cg*KNB+i] = (i<nv) ? (int)(cand[w][i]&0xffffffffu) : fb;
    if (lane==0) cnt_out[cg]=nv;
}

// ---- consolidated weight prep (validated R9/R10) ----
__device__ __forceinline__ void prep_one(const float* W, __nv_bfloat16* hi, __nv_bfloat16* lo,
                                         int K, int N, int Kpad, int t)
{
    int n = t / Kpad, k = t % Kpad;
    float v = (k < K) ? W[(size_t)k*N + n] : 0.f;
    splitf(v, hi[t], lo[t]);
}

__global__ void wprep_all_kernel(
    const float* W1b, const float* W1c, const float* W2b, const float* W2c,
    const float* W3a, const float* W3b, const float* W3c,
    __nv_bfloat16* w1bh, __nv_bfloat16* w1bl, __nv_bfloat16* w1ch, __nv_bfloat16* w1cl,
    __nv_bfloat16* w2bh, __nv_bfloat16* w2bl, __nv_bfloat16* w2ch, __nv_bfloat16* w2cl,
    __nv_bfloat16* w3ah, __nv_bfloat16* w3al, __nv_bfloat16* w3bh, __nv_bfloat16* w3bl,
    __nv_bfloat16* w3ch, __nv_bfloat16* w3cl)
{
    int t = blockIdx.x*256 + threadIdx.x;
    if      (t < 4096)          prep_one(W1b, w1bh, w1bl,  64,  64,  64, t);
    else if (t < 12288)         prep_one(W1c, w1ch, w1cl,  64, 128,  64, t-4096);
    else if (t < 28672)         prep_one(W2b, w2bh, w2bl, 128, 128, 128, t-12288);
    else if (t < 61440)         prep_one(W2c, w2ch, w2cl, 128, 256, 128, t-28672);
    else if (t < 135168)        prep_one(W3a, w3ah, w3al, 259, 256, 288, t-61440);
    else if (t < 266240)        prep_one(W3b, w3bh, w3bl, 256, 512, 256, t-135168);
    else if (t < 790528)        prep_one(W3c, w3ch, w3cl, 512,1024, 512, t-266240);
}

// ---- fused SA1 (persistent, grid 152) + y1 epilogue (R8) ----
__global__ void __launch_bounds__(256) sa1_fused_kernel(
    const float* __restrict__ pos, const float* __restrict__ pos1,
    const int* __restrict__ nidx, const int* __restrict__ cnt,
    const float* __restrict__ W1a, const float* __restrict__ b1a,
    const __nv_bfloat16* __restrict__ wbh, const __nv_bfloat16* __restrict__ wbl,
    const float* __restrict__ b1b,
    const __nv_bfloat16* __restrict__ wch, const __nv_bfloat16* __restrict__ wcl,
    const float* __restrict__ b1c,
    const float* __restrict__ W2a, const float* __restrict__ b2a,
    float* __restrict__ x1, float* __restrict__ y1)
{
    constexpr int S = 72;
    extern __shared__ __align__(16) char sm1[];
    __nv_bfloat16* AsH = (__nv_bfloat16*)sm1;
    __nv_bfloat16* AsL = AsH + 128*S;
    __nv_bfloat16* WcH = AsL + 128*S;
    __nv_bfloat16* WcL = WcH + 128*S;
    __nv_bfloat16* WbH = WcL + 128*S;
    __nv_bfloat16* WbL = WbH + 64*S;
    float* w1s   = (float*)(WbL + 64*S);
    float* colmax= w1s + 256;
    float* x1s   = colmax + 1024;
    float* w2as  = x1s + 256;

    const int tid=threadIdx.x, lane=tid&31, wid=tid>>5;
    const int wm=wid&3, wn=wid>>2;

    for (int t=tid; t<64*64;  t+=256){ int n=t>>6,k=t&63; WbH[n*S+k]=wbh[t]; WbL[n*S+k]=wbl[t]; }
    for (int t=tid; t<128*64; t+=256){ int n=t>>6,k=t&63; WcH[n*S+k]=wch[t]; WcL[n*S+k]=wcl[t]; }
    for (int t=tid; t<16384; t+=256) w2as[t]=W2a[t];
    if (tid<128) w2as[16384+tid]=b2a[tid];
    if (tid<192) w1s[tid]=W1a[tid];
    else if (tid<256) w1s[tid]=b1a[tid-192];

    const int NT = BATCH*M1C/2;
    for (int tile = blockIdx.x; tile < NT; tile += gridDim.x) {
        const int cg0 = tile*2;
        __syncthreads();
        {
            const int row=tid>>1, h0=(tid&1)*32;
            const int cg = cg0 + (row>>6);
            const int p  = nidx[cg*64 + (row&63)];
            const int src = (cg>>10)*NPT + p;
            const float rx = pos[3*src]  -pos1[3*cg];
            const float ry = pos[3*src+1]-pos1[3*cg+1];
            const float rz = pos[3*src+2]-pos1[3*cg+2];
#pragma unroll
            for (int j=0;j<32;++j){
                int n=h0+j;
                float v=fmaxf(rx*w1s[n]+ry*w1s[64+n]+rz*w1s[128+n]+w1s[192+n],0.f);
                splitf(v, AsH[row*S+n], AsL[row*S+n]);
            }
        }
        __syncthreads();

        float acc[2][8][4];
#pragma unroll
        for (int mf=0;mf<2;++mf)
#pragma unroll
            for (int nf=0;nf<4;++nf)
#pragma unroll
                for (int q=0;q<4;++q) acc[mf][nf][q]=0.f;
        mma_block<4,4,S>(acc, AsH, AsL, WbH, WbL, wm, wn*32, lane);
        __syncthreads();
#pragma unroll
        for (int mf=0;mf<2;++mf)
#pragma unroll
            for (int nf=0;nf<4;++nf){
                int r=wm*32+mf*16+(lane>>2);
                int c=wn*32+nf*8+(lane&3)*2;
                float b0=b1b[c], b1v=b1b[c+1];
                float v00=fmaxf(acc[mf][nf][0]+b0,0.f), v01=fmaxf(acc[mf][nf][1]+b1v,0.f);
                float v10=fmaxf(acc[mf][nf][2]+b0,0.f), v11=fmaxf(acc[mf][nf][3]+b1v,0.f);
                __nv_bfloat16 h0,l0,h1,l1;
                splitf(v00,h0,l0); splitf(v01,h1,l1);
                __nv_bfloat162 hh,ll;
                hh.x=h0; hh.y=h1; ll.x=l0; ll.y=l1;
                *(__nv_bfloat162*)&AsH[r*S+c]=hh; *(__nv_bfloat162*)&AsL[r*S+c]=ll;
                splitf(v10,h0,l0); splitf(v11,h1,l1);
                hh.x=h0; hh.y=h1; ll.x=l0; ll.y=l1;
                *(__nv_bfloat162*)&AsH[(r+8)*S+c]=hh; *(__nv_bfloat162*)&AsL[(r+8)*S+c]=ll;
            }
        __syncthreads();

#pragma unroll
        for (int mf=0;mf<2;++mf)
#pragma unroll
            for (int nf=0;nf<8;++nf)
#pragma unroll
                for (int q=0;q<4;++q) acc[mf][nf][q]=0.f;
        mma_block<8,4,S>(acc, AsH, AsL, WcH, WcL, wm, wn*64, lane);

        const int cv0=cnt[cg0], cv1=cnt[cg0+1];
#pragma unroll
        for (int nf=0;nf<8;++nf){
            int c=wn*64+nf*8+(lane&3)*2;
            float b0=b1c[c], b1v=b1c[c+1];
            float m0=-FLT_MAX, m1=-FLT_MAX;
#pragma unroll
            for (int mf=0;mf<2;++mf){
                int r=wm*32+mf*16+(lane>>2);
                int cv=(r>>6)?cv1:cv0;
                int rl=r&63;
                if (rl   < cv){ m0=fmaxf(m0,acc[mf][nf][0]+b0); m1=fmaxf(m1,acc[mf][nf][1]+b1v); }
                if (rl+8 < cv){ m0=fmaxf(m0,acc[mf][nf][2]+b0); m1=fmaxf(m1,acc[mf][nf][3]+b1v); }
            }
#pragma unroll
            for (int off=4; off<32; off<<=1){
                m0=fmaxf(m0,__shfl_xor_sync(0xffffffffu,m0,off));
                m1=fmaxf(m1,__shfl_xor_sync(0xffffffffu,m1,off));
            }
            if (lane<4){ colmax[wid*128+c]=m0; colmax[wid*128+c+1]=m1; }
        }
        __syncthreads();
        {
            int cent=tid>>7, col=tid&127;
            int wb=(col>>6)*4 + cent*2;
            float m=fmaxf(colmax[wb*128+col], colmax[(wb+1)*128+col]);
            int cv = cent? cv1:cv0;
            float xv = cv? m : 0.f;
            x1[(size_t)(cg0+cent)*128+col] = xv;
            x1s[tid] = xv;
        }
        __syncthreads();
        {
            int cent=tid>>7, col=tid&127;
            const float* xr = x1s + cent*128;
            float s = w2as[16384+col];
            for (int k = 0; k < 128; ++k)
                s += xr[k]*w2as[k*128+col];
            y1[(size_t)(cg0+cent)*128+col] = s;
        }
    }
}

// ---- fused SA2 (R8) ----
__global__ void __launch_bounds__(256) sa2_fused_kernel(
    const float* __restrict__ y1, const float* __restrict__ pos1,
    const float* __restrict__ pos2, const int* __restrict__ nidx,
    const int* __restrict__ cnt, const float* __restrict__ W2a,
    const __nv_bfloat16* __restrict__ wbh, const __nv_bfloat16* __restrict__ wbl,
    const float* __restrict__ b2b,
    const __nv_bfloat16* __restrict__ wch, const __nv_bfloat16* __restrict__ wcl,
    const float* __restrict__ b2c,
    float* __restrict__ x2)
{
    constexpr int S = 136;
    extern __shared__ __align__(16) char sm2[];
    __nv_bfloat16* AsH = (__nv_bfloat16*)sm2;
    __nv_bfloat16* AsL = AsH + 128*S;
    __nv_bfloat16* WsH = AsL + 128*S;
    __nv_bfloat16* WsL = WsH + 128*S;
    float* w2a3  = (float*)(WsL + 128*S);
    float* colmax= w2a3 + 384;

    const int tid=threadIdx.x, lane=tid&31, wid=tid>>5;
    const int wm=wid&3, wn=wid>>2;
    const int cg0 = blockIdx.x*2;

    for (int t=tid; t<384; t+=256) w2a3[t]=W2a[16384+t];
    for (int t=tid; t<16384; t+=256){ int n=t>>7,k=t&127; WsH[n*S+k]=wbh[t]; WsL[n*S+k]=wbl[t]; }
    __syncthreads();

    {
        const int row=tid>>1, h0=(tid&1)*64;
        const int cg = cg0 + (row>>6);
        const int gp = (cg>>8)*M1C + nidx[cg*64 + (row&63)];
        const float rx = pos1[3*gp]  -pos2[3*cg];
        const float ry = pos1[3*gp+1]-pos2[3*cg+1];
        const float rz = pos1[3*gp+2]-pos2[3*cg+2];
        const float* yr = y1 + (size_t)gp*128;
#pragma unroll
        for (int j=0;j<64;++j){
            int n=h0+j;
            float v=fmaxf(yr[n]+rx*w2a3[n]+ry*w2a3[128+n]+rz*w2a3[256+n],0.f);
            splitf(v, AsH[row*S+n], AsL[row*S+n]);
        }
    }
    __syncthreads();

    float acc[2][8][4];
#pragma unroll
    for (int mf=0;mf<2;++mf)
#pragma unroll
        for (int nf=0;nf<8;++nf)
#pragma unroll
            for (int q=0;q<4;++q) acc[mf][nf][q]=0.f;
    mma_block<8,8,S>(acc, AsH, AsL, WsH, WsL, wm, wn*64, lane);
    __syncthreads();
#pragma unroll
    for (int mf=0;mf<2;++mf)
#pragma unroll
        for (int nf=0;nf<8;++nf){
            int r=wm*32+mf*16+(lane>>2);
            int c=wn*64+nf*8+(lane&3)*2;
            float b0=b2b[c], b1v=b2b[c+1];
            float v00=fmaxf(acc[mf][nf][0]+b0,0.f), v01=fmaxf(acc[mf][nf][1]+b1v,0.f);
            float v10=fmaxf(acc[mf][nf][2]+b0,0.f), v11=fmaxf(acc[mf][nf][3]+b1v,0.f);
            __nv_bfloat16 h0,l0,h1,l1;
            splitf(v00,h0,l0); splitf(v01,h1,l1);
            __nv_bfloat162 hh,ll;
            hh.x=h0; hh.y=h1; ll.x=l0; ll.y=l1;
            *(__nv_bfloat162*)&AsH[r*S+c]=hh; *(__nv_bfloat162*)&AsL[r*S+c]=ll;
            splitf(v10,h0,l0); splitf(v11,h1,l1);
            hh.x=h0; hh.y=h1; ll.x=l0; ll.y=l1;
            *(__nv_bfloat162*)&AsH[(r+8)*S+c]=hh; *(__nv_bfloat162*)&AsL[(r+8)*S+c]=ll;
        }

    const int cv0=cnt[cg0], cv1=cnt[cg0+1];
#pragma unroll
    for (int half=0; half<2; ++half){
        __syncthreads();
        for (int t=tid; t<16384; t+=256){
            int n=t>>7,k=t&127;
            WsH[n*S+k]=wch[half*16384+t]; WsL[n*S+k]=wcl[half*16384+t];
        }
        __syncthreads();
#pragma unroll
        for (int mf=0;mf<2;++mf)
#pragma unroll
            for (int nf=0;nf<8;++nf)
#pragma unroll
                for (int q=0;q<4;++q) acc[mf][nf][q]=0.f;
        mma_block<8,8,S>(acc, AsH, AsL, WsH, WsL, wm, wn*64, lane);
#pragma unroll
        for (int nf=0;nf<8;++nf){
            int c=wn*64+nf*8+(lane&3)*2;
            float b0=b2c[half*128+c], b1v=b2c[half*128+c+1];
            float m0=-FLT_MAX, m1=-FLT_MAX;
#pragma unroll
            for (int mf=0;mf<2;++mf){
                int r=wm*32+mf*16+(lane>>2);
                int cv=(r>>6)?cv1:cv0;
                int rl=r&63;
                if (rl   < cv){ m0=fmaxf(m0,acc[mf][nf][0]+b0); m1=fmaxf(m1,acc[mf][nf][1]+b1v); }
                if (rl+8 < cv){ m0=fmaxf(m0,acc[mf][nf][2]+b0); m1=fmaxf(m1,acc[mf][nf][3]+b1v); }
            }
#pragma unroll
            for (int off=4; off<32; off<<=1){
                m0=fmaxf(m0,__shfl_xor_sync(0xffffffffu,m0,off));
                m1=fmaxf(m1,__shfl_xor_sync(0xffffffffu,m1,off));
            }
            if (lane<4){ colmax[wid*128+c]=m0; colmax[wid*128+c+1]=m1; }
        }
        __syncthreads();
        {
            int cent=tid>>7, col=tid&127;
            int wb=(col>>6)*4 + cent*2;
            float m=fmaxf(colmax[wb*128+col], colmax[(wb+1)*128+col]);
            int cv = cent? cv1:cv0;
            x2[(size_t)(cg0+cent)*256 + half*128 + col] = cv? m : 0.f;
        }
    }
}

// ---- generic tensor-core GEMM: 128x64 tile, split bf16 ----
__global__ void __launch_bounds__(256) mma_gemm_kernel(
    const __nv_bfloat16* __restrict__ Ahi, const __nv_bfloat16* __restrict__ Alo,
    const __nv_bfloat16* __restrict__ Whi, const __nv_bfloat16* __restrict__ Wlo,
    const float* __restrict__ bias,
    float* __restrict__ outF,
    __nv_bfloat16* __restrict__ outHi, __nv_bfloat16* __restrict__ outLo,
    int N, int K, int relu)
{
    __shared__ __nv_bfloat16 AsH[128][34], AsL[128][34], WsH[64][34], WsL[64][34];
    const int tid = threadIdx.x;
    const int lane = tid & 31, wid = tid >> 5;
    const int wm = wid & 3, wn = wid >> 2;
    const int bm = blockIdx.y*128, bn = blockIdx.x*64;
    const int tcol = (tid & 15)*2, trow = tid >> 4;

    float acc[2][4][4];
#pragma unroll
    for (int mf=0; mf<2; ++mf)
#pragma unroll
        for (int nf=0; nf<4; ++nf)
#pragma unroll
            for (int q=0; q<4; ++q) acc[mf][nf][q]=0.f;

    for (int k0 = 0; k0 < K; k0 += 32) {
#pragma unroll
        for (int p = 0; p < 8; ++p) {
            int r = trow + p*16;
            size_t ga = (size_t)(bm + r)*K + k0 + tcol;
            *(unsigned*)&AsH[r][tcol] = *(const unsigned*)&Ahi[ga];
            *(unsigned*)&AsL[r][tcol] = *(const unsigned*)&Alo[ga];
        }
#pragma unroll
        for (int p = 0; p < 4; ++p) {
            int n = trow + p*16;
            size_t gw = (size_t)(bn + n)*K + k0 + tcol;
            *(unsigned*)&WsH[n][tcol] = *(const unsigned*)&Whi[gw];
            *(unsigned*)&WsL[n][tcol] = *(const unsigned*)&Wlo[gw];
        }
        __syncthreads();
#pragma unroll
        for (int ks = 0; ks < 2; ++ks) {
            const int kk = ks*16 + (lane&3)*2;
            unsigned ah[2][4], al[2][4], bh[4][2], bl[4][2];
#pragma unroll
            for (int mf=0; mf<2; ++mf) {
                int r = wm*32 + mf*16 + (lane>>2);
                ah[mf][0]=*(const unsigned*)&AsH[r][kk];
                ah[mf][1]=*(const unsigned*)&AsH[r+8][kk];
                ah[mf][2]=*(const unsigned*)&AsH[r][kk+8];
                ah[mf][3]=*(const unsigned*)&AsH[r+8][kk+8];
                al[mf][0]=*(const unsigned*)&AsL[r][kk];
                al[mf][1]=*(const unsigned*)&AsL[r+8][kk];
                al[mf][2]=*(const unsigned*)&AsL[r][kk+8];
                al[mf][3]=*(const unsigned*)&AsL[r+8][kk+8];
            }
#pragma unroll
            for (int nf=0; nf<4; ++nf) {
                int n = wn*32 + nf*8 + (lane>>2);
                bh[nf][0]=*(const unsigned*)&WsH[n][kk];
                bh[nf][1]=*(const unsigned*)&WsH[n][kk+8];
                bl[nf][0]=*(const unsigned*)&WsL[n][kk];
                bl[nf][1]=*(const unsigned*)&WsL[n][kk+8];
            }
#pragma unroll
            for (int mf=0; mf<2; ++mf)
#pragma unroll
                for (int nf=0; nf<4; ++nf) {
                    mma16816(acc[mf][nf], ah[mf], bh[nf]);
                    mma16816(acc[mf][nf], ah[mf], bl[nf]);
                    mma16816(acc[mf][nf], al[mf], bh[nf]);
                }
        }
        __syncthreads();
    }

#pragma unroll
    for (int mf=0; mf<2; ++mf)
#pragma unroll
        for (int nf=0; nf<4; ++nf) {
            int r = bm + wm*32 + mf*16 + (lane>>2);
            int c = bn + wn*32 + nf*8 + (lane&3)*2;
            float b0 = bias[c], b1 = bias[c+1];
            float v00 = acc[mf][nf][0]+b0, v01 = acc[mf][nf][1]+b1;
            float v10 = acc[mf][nf][2]+b0, v11 = acc[mf][nf][3]+b1;
            if (relu) {
                v00=fmaxf(v00,0.f); v01=fmaxf(v01,0.f);
                v10=fmaxf(v10,0.f); v11=fmaxf(v11,0.f);
            }
            if (outF) {
                outF[(size_t)r*N + c]   = v00; outF[(size_t)r*N + c+1]   = v01;
                outF[(size_t)(r+8)*N+c] = v10; outF[(size_t)(r+8)*N+c+1] = v11;
            }
            if (outHi) {
                __nv_bfloat16 h0,l0,h1,l1;
                splitf(v00,h0,l0); splitf(v01,h1,l1);
                __nv_bfloat162 hh; hh.x=h0; hh.y=h1;
                __nv_bfloat162 ll; ll.x=l0; ll.y=l1;
                *(__nv_bfloat162*)&outHi[(size_t)r*N + c] = hh;
                *(__nv_bfloat162*)&outLo[(size_t)r*N + c] = ll;
                splitf(v10,h0,l0); splitf(v11,h1,l1);
                hh.x=h0; hh.y=h1; ll.x=l0; ll.y=l1;
                *(__nv_bfloat162*)&outHi[(size_t)(r+8)*N + c] = hh;
                *(__nv_bfloat162*)&outLo[(size_t)(r+8)*N + c] = ll;
            }
        }
}

// ---- SA3 feature build ----
__global__ void feats3_split_kernel(const float* __restrict__ x2, const float* __restrict__ pos2,
                                    __nv_bfloat16* __restrict__ hi, __nv_bfloat16* __restrict__ lo)
{
    int row = blockIdx.x*2 + (threadIdx.x>>7);
    int c0 = threadIdx.x & 127;
    for (int c = c0; c < 288; c += 128) {
        float v = (c < 256) ? x2[(size_t)row*256 + c]
                : (c < 259) ? pos2[row*3 + c - 256] : 0.f;
        splitf(v, hi[(size_t)row*288 + c], lo[(size_t)row*288 + c]);
    }
}

__global__ void pool256_kernel(const float* __restrict__ g, float* __restrict__ gfeat)
{
    int b = blockIdx.y, f = blockIdx.x*256 + threadIdx.x;
    float m = -FLT_MAX;
    for (int r = 0; r < M2C; ++r)
        m = fmaxf(m, g[(size_t)(b*M2C+r)*1024 + f]);
    gfeat[b*1024+f]=m;
}

__global__ void head_kernel(const float* __restrict__ gfeat,
                            const float* __restrict__ Wh1, const float* __restrict__ bh1,
                            const float* __restrict__ Wh2, const float* __restrict__ bh2,
                            const float* __restrict__ Wh3, const float* __restrict__ bh3,
                            float* __restrict__ out)
{
    __shared__ float gf[1024], h1[512], h2[256], lg[10];
    const int b=blockIdx.x, tid=threadIdx.x;
    for (int i = tid; i < 1024; i += 256) gf[i]=gfeat[b*1024+i];
    __syncthreads();
    for (int n = tid; n < 512; n += 256) {
        float s = bh1[n];
        for (int k = 0; k < 1024; ++k) s += gf[k]*Wh1[(size_t)k*512+n];
        h1[n]=fmaxf(s,0.f);
    }
    __syncthreads();
    { float s = bh2[tid];
      for (int k = 0; k < 512; ++k) s += h1[k]*Wh2[(size_t)k*256+tid];
      h2[tid]=fmaxf(s,0.f); }
    __syncthreads();
    if (tid < 10) {
        float s = bh3[tid];
        for (int k = 0; k < 256; ++k) s += h2[k]*Wh3[k*10+tid];
        lg[tid]=s;
    }
    __syncthreads();
    if (tid == 0) {
        float m=lg[0];
        for (int j=1;j<10;++j) m=fmaxf(m,lg[j]);
        float se=0.f;
        for (int j=0;j<10;++j) se+=expf(lg[j]-m);
        float l=logf(se);
        for (int j=0;j<10;++j) out[b*10+j]=lg[j]-m-l;
    }
}

extern "C" void kernel_launch(void* const* d_in, const int* in_sizes, int n_in,
                              void* d_out, int out_size)
{
    const float* pos=(const float*)d_in[0];
    const float *W1a=(const float*)d_in[1],  *b1a=(const float*)d_in[2];
    const float *W1b=(const float*)d_in[3],  *b1b=(const float*)d_in[4];
    const float *W1c=(const float*)d_in[5],  *b1c=(const float*)d_in[6];
    const float *W2a=(const float*)d_in[7],  *b2a=(const float*)d_in[8];
    const float *W2b=(const float*)d_in[9],  *b2b=(const float*)d_in[10];
    const float *W2c=(const float*)d_in[11], *b2c=(const float*)d_in[12];
    const float *W3a=(const float*)d_in[13], *b3a=(const float*)d_in[14];
    const float *W3b=(const float*)d_in[15], *b3b=(const float*)d_in[16];
    const float *W3c=(const float*)d_in[17], *b3c=(const float*)d_in[18];
    const float *Wh1=(const float*)d_in[19], *bh1=(const float*)d_in[20];
    const float *Wh2=(const float*)d_in[21], *bh2=(const float*)d_in[22];
    const float *Wh3=(const float*)d_in[23], *bh3=(const float*)d_in[24];

    float *curv,*pos1,*curv1,*pos2,*x1,*x2,*gfeat,*fF,*bA;
    int *nidx1,*cnt1,*nidx2,*cnt2;
    __nv_bfloat16 *w1bh,*w1bl,*w1ch,*w1cl,*w2bh,*w2bl,*w2ch,*w2cl;
    __nv_bfloat16 *w3ah,*w3al,*w3bh,*w3bl,*w3ch,*w3cl;
    __nv_bfloat16 *pAh,*pAl,*pBh,*pBl,*pCh,*pCl;
    cudaGetSymbolAddress((void**)&curv, g_curv);
    cudaGetSymbolAddress((void**)&pos1, g_pos1);
    cudaGetSymbolAddress((void**)&curv1,g_curv1);
    cudaGetSymbolAddress((void**)&pos2, g_pos2);
    cudaGetSymbolAddress((void**)&nidx1,g_nidx1);
    cudaGetSymbolAddress((void**)&cnt1, g_cnt1);
    cudaGetSymbolAddress((void**)&nidx2,g_nidx2);
    cudaGetSymbolAddress((void**)&cnt2, g_cnt2);
    cudaGetSymbolAddress((void**)&x1,   g_x1);
    cudaGetSymbolAddress((void**)&x2,   g_x2);
    cudaGetSymbolAddress((void**)&gfeat,g_gfeat);
    cudaGetSymbolAddress((void**)&fF,   g_featF);
    cudaGetSymbolAddress((void**)&bA,   g_bufA);
    cudaGetSymbolAddress((void**)&w1bh, g_w1bh); cudaGetSymbolAddress((void**)&w1bl, g_w1bl);
    cudaGetSymbolAddress((void**)&w1ch, g_w1ch); cudaGetSymbolAddress((void**)&w1cl, g_w1cl);
    cudaGetSymbolAddress((void**)&w2bh, g_w2bh); cudaGetSymbolAddress((void**)&w2bl, g_w2bl);
    cudaGetSymbolAddress((void**)&w2ch, g_w2ch); cudaGetSymbolAddress((void**)&w2cl, g_w2cl);
    cudaGetSymbolAddress((void**)&w3ah, g_w3ah); cudaGetSymbolAddress((void**)&w3al, g_w3al);
    cudaGetSymbolAddress((void**)&w3bh, g_w3bh); cudaGetSymbolAddress((void**)&w3bl, g_w3bl);
    cudaGetSymbolAddress((void**)&w3ch, g_w3ch); cudaGetSymbolAddress((void**)&w3cl, g_w3cl);
    cudaGetSymbolAddress((void**)&pAh,  g_pAh);  cudaGetSymbolAddress((void**)&pAl,  g_pAl);
    cudaGetSymbolAddress((void**)&pBh,  g_pBh);  cudaGetSymbolAddress((void**)&pBl,  g_pBl);
    cudaGetSymbolAddress((void**)&pCh,  g_pCh);  cudaGetSymbolAddress((void**)&pCl,  g_pCl);

    cudaFuncSetAttribute(sa1_fused_kernel, cudaFuncAttributeMaxDynamicSharedMemorySize, 164352);
    cudaFuncSetAttribute(sa2_fused_kernel, cudaFuncAttributeMaxDynamicSharedMemorySize, 144896);

    cudaStream_t s2; cudaStreamCreateWithFlags(&s2, cudaStreamNonBlocking);
    cudaEvent_t e0, eW, e1, e2;
    cudaEventCreateWithFlags(&e0, cudaEventDisableTiming);
    cudaEventCreateWithFlags(&eW, cudaEventDisableTiming);
    cudaEventCreateWithFlags(&e1, cudaEventDisableTiming);
    cudaEventCreateWithFlags(&e2, cudaEventDisableTiming);

    // node 1: consolidated weight prep on s2
    cudaEventRecord(e0, 0);
    cudaStreamWaitEvent(s2, e0, 0);
    wprep_all_kernel<<<3088, 256, 0, s2>>>(W1b, W1c, W2b, W2c, W3a, W3b, W3c,
        w1bh, w1bl, w1ch, w1cl, w2bh, w2bl, w2ch, w2cl,
        w3ah, w3al, w3bh, w3bl, w3ch, w3cl);
    cudaEventRecord(eW, s2);

    // nodes 2-5: curvature, fps1, group1, dummy (main)
    curvature_kernel<<<BATCH*(NPT/128), 128>>>(pos, curv);
    fps_kernel<NPT,M1C><<<BATCH, 256>>>(pos, curv, pos1, curv1);
    cudaEventRecord(e1, 0);
    group_kernel<NPT,128,8><<<dim3(M1C/8, BATCH), 256>>>(pos, pos1, nidx1, cnt1, M1C, 0.04f);
    dummy_kernel<<<1, 32>>>();

    // node 6: SA1 <- ncu capture slot
    cudaStreamWaitEvent(0, eW, 0);
    sa1_fused_kernel<<<152, 256, 164352>>>(pos, pos1, nidx1, cnt1,
        W1a, b1a, w1bh, w1bl, b1b, w1ch, w1cl, b1c, W2a, b2a, x1, fF);

    // branch B on s2 (event-gated on e1; runs concurrent with group1/SA1)
    cudaStreamWaitEvent(s2, e1, 0);
    fps_kernel<M1C,M2C><<<BATCH, 256, 0, s2>>>(pos1, curv1, pos2, (float*)0);
    group_kernel<M1C,512,4><<<dim3(M2C/4, BATCH), 128, 0, s2>>>(pos1, pos2, nidx2, cnt2, M2C, 0.16f);
    cudaEventRecord(e2, s2);

    // join, SA2
    cudaStreamWaitEvent(0, e2, 0);
    sa2_fused_kernel<<<BATCH*M2C/2, 256, 144896>>>(fF, pos1, pos2, nidx2, cnt2,
        W2a, w2bh, w2bl, b2b, w2ch, w2cl, b2c, x2);

    // SA3 on tensor cores
    feats3_split_kernel<<<BATCH*M2C/2, 256>>>(x2, pos2, pAh, pAl);
    mma_gemm_kernel<<<dim3(4, 16), 256>>>(pAh, pAl, w3ah, w3al, b3a,
                                          (float*)0, pBh, pBl, 256, 288, 1);
    mma_gemm_kernel<<<dim3(8, 16), 256>>>(pBh, pBl, w3bh, w3bl, b3b,
                                          (float*)0, pCh, pCl, 512, 256, 1);
    mma_gemm_kernel<<<dim3(16, 16), 256>>>(pCh, pCl, w3ch, w3cl, b3c,
                                           bA, (__nv_bfloat16*)0, (__nv_bfloat16*)0, 1024, 512, 0);
    pool256_kernel<<<dim3(4, BATCH), 256>>>(bA, gfeat);

    // head
    head_kernel<<<BATCH, 256>>>(gfeat, Wh1, bh1, Wh2, bh2, Wh3, bh3, (float*)d_out);
}

// round 14
// speedup vs baseline: 1.2027x; 1.2027x over previous
#include <cuda_runtime.h>
#include <cuda_bf16.h>
#include <math.h>
#include <float.h>

#define BATCH 8
#define NPT   2048
#define M1C   1024
#define M2C   256
#define KNB   64
#define CURVK 10

// ---- scratch (device globals; no allocation) ----
__device__ float g_curv [BATCH*NPT];
__device__ float g_pos1 [BATCH*M1C*3];
__device__ float g_curv1[BATCH*M1C];
__device__ float g_pos2 [BATCH*M2C*3];
__device__ int   g_nidx1[BATCH*M1C*KNB];
__device__ int   g_cnt1 [BATCH*M1C];
__device__ int   g_nidx2[BATCH*M2C*KNB];
__device__ int   g_cnt2 [BATCH*M2C];
__device__ float g_x1   [BATCH*M1C*128];
__device__ float g_x2   [BATCH*M2C*256];
__device__ float g_gfeat[BATCH*1024];
__device__ float g_featF[1024*1024];          // y1 (8192x128)
__device__ float g_bufA [2*1024*1024];        // SA3 final fp32 (2048x1024)
__device__ __nv_bfloat16 g_w1bh[4096],  g_w1bl[4096];
__device__ __nv_bfloat16 g_w1ch[8192],  g_w1cl[8192];
__device__ __nv_bfloat16 g_w2bh[16384], g_w2bl[16384];
__device__ __nv_bfloat16 g_w2ch[32768], g_w2cl[32768];
__device__ __nv_bfloat16 g_w3ah[73728], g_w3al[73728];
__device__ __nv_bfloat16 g_w3bh[131072],g_w3bl[131072];
__device__ __nv_bfloat16 g_w3ch[524288],g_w3cl[524288];
__device__ __nv_bfloat16 g_pAh[589824], g_pAl[589824];
__device__ __nv_bfloat16 g_pBh[524288], g_pBl[524288];
__device__ __nv_bfloat16 g_pCh[1048576],g_pCl[1048576];

__device__ __forceinline__ void splitf(float v, __nv_bfloat16& h, __nv_bfloat16& l) {
    h = __float2bfloat16(v);
    l = __float2bfloat16(v - __bfloat162float(h));
}

__device__ __forceinline__ void mma16816(float* c, const unsigned* a, const unsigned* b) {
    asm volatile(
      "mma.sync.aligned.m16n8k16.row.col.f32.bf16.bf16.f32 "
      "{%0,%1,%2,%3}, {%4,%5,%6,%7}, {%8,%9}, {%0,%1,%2,%3};\n"
      : "+f"(c[0]), "+f"(c[1]), "+f"(c[2]), "+f"(c[3])
      : "r"(a[0]), "r"(a[1]), "r"(a[2]), "r"(a[3]), "r"(b[0]), "r"(b[1]));
}

template<int NF,int K16,int S>
__device__ __forceinline__ void mma_block(
    float (&acc)[2][8][4],
    const __nv_bfloat16* AsH, const __nv_bfloat16* AsL,
    const __nv_bfloat16* WH,  const __nv_bfloat16* WL,
    int wm, int wnbase, int lane)
{
#pragma unroll
    for (int k16=0;k16<K16;++k16){
        const int kk=k16*16+(lane&3)*2;
        unsigned ah[2][4], al[2][4];
#pragma unroll
        for (int mf=0;mf<2;++mf){
            int r=wm*32+mf*16+(lane>>2);
            ah[mf][0]=*(const unsigned*)&AsH[r*S+kk];
            ah[mf][1]=*(const unsigned*)&AsH[(r+8)*S+kk];
            ah[mf][2]=*(const unsigned*)&AsH[r*S+kk+8];
            ah[mf][3]=*(const unsigned*)&AsH[(r+8)*S+kk+8];
            al[mf][0]=*(const unsigned*)&AsL[r*S+kk];
            al[mf][1]=*(const unsigned*)&AsL[(r+8)*S+kk];
            al[mf][2]=*(const unsigned*)&AsL[r*S+kk+8];
            al[mf][3]=*(const unsigned*)&AsL[(r+8)*S+kk+8];
        }
#pragma unroll
        for (int nf=0;nf<NF;++nf){
            int n=wnbase+nf*8+(lane>>2);
            unsigned bh[2]={*(const unsigned*)&WH[n*S+kk], *(const unsigned*)&WH[n*S+kk+8]};
            unsigned bl[2]={*(const unsigned*)&WL[n*S+kk], *(const unsigned*)&WL[n*S+kk+8]};
#pragma unroll
            for (int mf=0;mf<2;++mf){
                mma16816(acc[mf][nf], ah[mf], bh);
                mma16816(acc[mf][nf], ah[mf], bl);
                mma16816(acc[mf][nf], al[mf], bh);
            }
        }
    }
}

// ---- curvature ----
__global__ void curvature_kernel(const float* __restrict__ pos, float* __restrict__ curv)
{
    __shared__ float px[NPT], py[NPT], pz[NPT], nr[NPT];
    const int b = blockIdx.x / (NPT/128);
    const int tid = threadIdx.x;
    const float* cp = pos + (size_t)b * NPT * 3;
    for (int i = tid; i < NPT; i += 128) {
        float x = cp[3*i], y = cp[3*i+1], z = cp[3*i+2];
        px[i]=x; py[i]=y; pz[i]=z; nr[i]=x*x+y*y+z*z;
    }
    __syncthreads();
    const int i = (blockIdx.x % (NPT/128)) * 128 + tid;
    const float qx=px[i], qy=py[i], qz=pz[i], nq=nr[i];

    float td[CURVK]; int ti[CURVK];
#pragma unroll
    for (int s = 0; s < CURVK; ++s) { td[s]=3.4e38f; ti[s]=0; }
#pragma unroll 8
    for (int j = 0; j < NPT; ++j) {
        float d2 = nq + nr[j] - 2.0f*(qx*px[j]+qy*py[j]+qz*pz[j]);
        if (d2 < td[CURVK-1]) {
            float cd=d2; int ci=j;
#pragma unroll
            for (int s = 0; s < CURVK; ++s)
                if (cd < td[s]) { float t=td[s]; td[s]=cd; cd=t; int u=ti[s]; ti[s]=ci; ci=u; }
        }
    }
    float mx=0,my=0,mz=0;
#pragma unroll
    for (int s = 0; s < CURVK; ++s) { mx+=px[ti[s]]; my+=py[ti[s]]; mz+=pz[ti[s]]; }
    mx/=CURVK; my/=CURVK; mz/=CURVK;
    double cxx=0,cxy=0,cxz=0,cyy=0,cyz=0,czz=0;
#pragma unroll
    for (int s = 0; s < CURVK; ++s) {
        float ax=px[ti[s]]-mx, ay=py[ti[s]]-my, az=pz[ti[s]]-mz;
        cxx+=(double)ax*ax; cxy+=(double)ax*ay; cxz+=(double)ax*az;
        cyy+=(double)ay*ay; cyz+=(double)ay*az; czz+=(double)az*az;
    }
    cxx/=CURVK; cxy/=CURVK; cxz/=CURVK; cyy/=CURVK; cyz/=CURVK; czz/=CURVK;
    double tr=cxx+cyy+czz;
    double p1=cxy*cxy+cxz*cxz+cyz*cyz;
    double q=tr/3.0;
    double p2=(cxx-q)*(cxx-q)+(cyy-q)*(cyy-q)+(czz-q)*(czz-q)+2.0*p1;
    double lmin;
    if (p2 < 1e-32) lmin = q;
    else {
        double p=sqrt(p2/6.0);
        double b00=(cxx-q)/p,b11=(cyy-q)/p,b22=(czz-q)/p,b01=cxy/p,b02=cxz/p,b12=cyz/p;
        double detB=b00*(b11*b22-b12*b12)-b01*(b01*b22-b12*b02)+b02*(b01*b12-b11*b02);
        double r=fmin(1.0,fmax(-1.0,detB*0.5));
        lmin=q+2.0*p*cos(acos(r)/3.0 + 2.0943951023931953);
    }
    curv[b*NPT+i]=(float)(lmin/(tr+1e-8));
}

// ---- weighted FPS with fused gather (R8 body, 256 thr) ----
template<int NPTS,int MOUT>
__global__ void __launch_bounds__(256) fps_kernel(const float* __restrict__ pos,
                                                  const float* __restrict__ curv,
                                                  float* __restrict__ opos,
                                                  float* __restrict__ ocurv)
{
    constexpr int THR=256, E=NPTS/THR, NW=8;
    __shared__ float spx[NPTS], spy[NPTS], spz[NPTS], scv[NPTS];
    __shared__ unsigned long long wkey[2][NW];
    const int b=blockIdx.x, tid=threadIdx.x, lane=tid&31, wid=tid>>5;
    const float* cp = pos + (size_t)b*NPTS*3;
    float px[E],py[E],pz[E],ww[E],md[E];
#pragma unroll
    for (int e=0;e<E;++e){
        int i=tid+e*THR;
        float x=cp[3*i], y=cp[3*i+1], z=cp[3*i+2];
        float cv=curv[b*NPTS+i];
        px[e]=x; py[e]=y; pz[e]=z;
        spx[i]=x; spy[i]=y; spz[i]=z; scv[i]=cv;
        ww[e]=1.0f+10.0f*cv;
        md[e]=FLT_MAX;
    }
    __syncthreads();
    float sx=spx[0], sy=spy[0], sz=spz[0];
    if (tid==0){
        int o=b*MOUT;
        opos[3*o]=sx; opos[3*o+1]=sy; opos[3*o+2]=sz;
        if (ocurv) ocurv[o]=scv[0];
    }
    for (int m=1;m<MOUT;++m){
        float bv=-1.f; int bi=0;
#pragma unroll
        for (int e=0;e<E;++e){
            int i=tid+e*THR;
            float dx=px[e]-sx, dy=py[e]-sy, dz=pz[e]-sz;
            float d=fminf(md[e], dx*dx+dy*dy+dz*dz);
            md[e]=d;
            float v=d*ww[e];
            if (v>bv){ bv=v; bi=i; }   // i increasing per thread -> first max kept
        }
        unsigned hv=__float_as_uint(bv);
        unsigned hm=__reduce_max_sync(0xffffffffu, hv);
        unsigned lm=__reduce_max_sync(0xffffffffu, (hv==hm)? ~(unsigned)bi : 0u);
        if (lane==0) wkey[m&1][wid]=((unsigned long long)hm<<32)|lm;
        __syncthreads();
        unsigned long long k2 = (lane<NW)? wkey[m&1][lane] : 0ull;
        unsigned h2=(unsigned)(k2>>32), l2=(unsigned)k2;
        unsigned hm2=__reduce_max_sync(0xffffffffu, h2);
        unsigned lm2=__reduce_max_sync(0xffffffffu, (h2==hm2)? l2 : 0u);
        int s=(int)(~lm2);
        sx=spx[s]; sy=spy[s]; sz=spz[s];
        if (tid==0){
            int o=b*MOUT+m;
            opos[3*o]=sx; opos[3*o+1]=sy; opos[3*o+2]=sz;
            if (ocurv) ocurv[o]=scv[s];
        }
    }
}

// ---- radius grouping (R8 config) ----
template<int NPTS,int CAP,int CPB>
__global__ void group_kernel(const float* __restrict__ pts, const float* __restrict__ cents,
                             int* __restrict__ nidx, int* __restrict__ cnt_out,
                             int MC, float r2)
{
    __shared__ float px[NPTS],py[NPTS],pz[NPTS],nr[NPTS];
    __shared__ unsigned long long cand[CPB][CAP];
    const int b=blockIdx.y, tid=threadIdx.x;
    const float* cp = pts + (size_t)b*NPTS*3;
    for (int i = tid; i < NPTS; i += CPB*32) {
        float x=cp[3*i],y=cp[3*i+1],z=cp[3*i+2];
        px[i]=x; py[i]=y; pz[i]=z; nr[i]=x*x+y*y+z*z;
    }
    __syncthreads();
    const int w=tid>>5, lane=tid&31;
    const int c=blockIdx.x*CPB+w, cg=b*MC+c;
    const float cx=cents[3*cg],cy=cents[3*cg+1],cz=cents[3*cg+2];
    const float nc=cx*cx+cy*cy+cz*cz;
    int cnt=0;
    for (int j0 = 0; j0 < NPTS; j0 += 32) {
        int j=j0+lane;
        float d2 = nc + nr[j] - 2.0f*(cx*px[j]+cy*py[j]+cz*pz[j]);
        bool in = (d2 <= r2);
        unsigned mask = __ballot_sync(0xffffffffu, in);
        if (in) {
            int p = cnt + __popc(mask & ((1u<<lane)-1u));
            if (p < CAP) {
                unsigned ub=__float_as_uint(d2);
                ub = (ub&0x80000000u) ? ~ub : (ub|0x80000000u);
                cand[w][p] = ((unsigned long long)ub<<32) | (unsigned)j;
            }
        }
        cnt += __popc(mask);
    }
    if (cnt > CAP) cnt = CAP;
    for (int i = cnt+lane; i < CAP; i += 32) cand[w][i]=0xFFFFFFFFFFFFFFFFull;
    __syncwarp();
    for (int k = 2; k <= CAP; k <<= 1)
        for (int j = k>>1; j > 0; j >>= 1) {
            for (int i = lane; i < CAP; i += 32) {
                int ixj = i^j;
                if (ixj > i) {
                    unsigned long long a=cand[w][i], bb=cand[w][ixj];
                    if ((a>bb) == ((i&k)==0)) { cand[w][i]=bb; cand[w][ixj]=a; }
                }
            }
            __syncwarp();
        }
    int nv = cnt < KNB ? cnt : KNB;
    int fb = (nv>0) ? (int)(cand[w][0]&0xffffffffu) : 0;
    for (int i = lane; i < KNB; i += 32)
        nidx[(size_t)cg*KNB+i] = (i<nv) ? (int)(cand[w][i]&0xffffffffu) : fb;
    if (lane==0) cnt_out[cg]=nv;
}

// ---- weight prep (R8: separate kernels) ----
__global__ void wprep_kernel(const float* __restrict__ W,
                             __nv_bfloat16* __restrict__ hi, __nv_bfloat16* __restrict__ lo,
                             int K, int N)
{
    int t = blockIdx.x*256 + threadIdx.x;
    if (t >= K*N) return;
    int n = t / K, k = t % K;
    __nv_bfloat16 h,l; splitf(W[(size_t)k*N + n], h, l);
    hi[t]=h; lo[t]=l;
}
__global__ void wprep_pad_kernel(const float* __restrict__ W,
                                 __nv_bfloat16* __restrict__ hi, __nv_bfloat16* __restrict__ lo,
                                 int K, int N, int Kpad)
{
    int t = blockIdx.x*256 + threadIdx.x;
    if (t >= N*Kpad) return;
    int n = t / Kpad, k = t % Kpad;
    float v = (k < K) ? W[(size_t)k*N + n] : 0.f;
    __nv_bfloat16 h,l; splitf(v, h, l);
    hi[t]=h; lo[t]=l;
}

// ---- fused SA1 (persistent, grid 152) + y1 epilogue (R8) ----
__global__ void __launch_bounds__(256) sa1_fused_kernel(
    const float* __restrict__ pos, const float* __restrict__ pos1,
    const int* __restrict__ nidx, const int* __restrict__ cnt,
    const float* __restrict__ W1a, const float* __restrict__ b1a,
    const __nv_bfloat16* __restrict__ wbh, const __nv_bfloat16* __restrict__ wbl,
    const float* __restrict__ b1b,
    const __nv_bfloat16* __restrict__ wch, const __nv_bfloat16* __restrict__ wcl,
    const float* __restrict__ b1c,
    const float* __restrict__ W2a, const float* __restrict__ b2a,
    float* __restrict__ x1, float* __restrict__ y1)
{
    constexpr int S = 72;
    extern __shared__ __align__(16) char sm1[];
    __nv_bfloat16* AsH = (__nv_bfloat16*)sm1;
    __nv_bfloat16* AsL = AsH + 128*S;
    __nv_bfloat16* WcH = AsL + 128*S;
    __nv_bfloat16* WcL = WcH + 128*S;
    __nv_bfloat16* WbH = WcL + 128*S;
    __nv_bfloat16* WbL = WbH + 64*S;
    float* w1s   = (float*)(WbL + 64*S);
    float* colmax= w1s + 256;
    float* x1s   = colmax + 1024;
    float* w2as  = x1s + 256;

    const int tid=threadIdx.x, lane=tid&31, wid=tid>>5;
    const int wm=wid&3, wn=wid>>2;

    for (int t=tid; t<64*64;  t+=256){ int n=t>>6,k=t&63; WbH[n*S+k]=wbh[t]; WbL[n*S+k]=wbl[t]; }
    for (int t=tid; t<128*64; t+=256){ int n=t>>6,k=t&63; WcH[n*S+k]=wch[t]; WcL[n*S+k]=wcl[t]; }
    for (int t=tid; t<16384; t+=256) w2as[t]=W2a[t];
    if (tid<128) w2as[16384+tid]=b2a[tid];
    if (tid<192) w1s[tid]=W1a[tid];
    else if (tid<256) w1s[tid]=b1a[tid-192];

    const int NT = BATCH*M1C/2;
    for (int tile = blockIdx.x; tile < NT; tile += gridDim.x) {
        const int cg0 = tile*2;
        __syncthreads();
        {
            const int row=tid>>1, h0=(tid&1)*32;
            const int cg = cg0 + (row>>6);
            const int p  = nidx[cg*64 + (row&63)];
            const int src = (cg>>10)*NPT + p;
            const float rx = pos[3*src]  -pos1[3*cg];
            const float ry = pos[3*src+1]-pos1[3*cg+1];
            const float rz = pos[3*src+2]-pos1[3*cg+2];
#pragma unroll
            for (int j=0;j<32;++j){
                int n=h0+j;
                float v=fmaxf(rx*w1s[n]+ry*w1s[64+n]+rz*w1s[128+n]+w1s[192+n],0.f);
                splitf(v, AsH[row*S+n], AsL[row*S+n]);
            }
        }
        __syncthreads();

        float acc[2][8][4];
#pragma unroll
        for (int mf=0;mf<2;++mf)
#pragma unroll
            for (int nf=0;nf<4;++nf)
#pragma unroll
                for (int q=0;q<4;++q) acc[mf][nf][q]=0.f;
        mma_block<4,4,S>(acc, AsH, AsL, WbH, WbL, wm, wn*32, lane);
        __syncthreads();
#pragma unroll
        for (int mf=0;mf<2;++mf)
#pragma unroll
            for (int nf=0;nf<4;++nf){
                int r=wm*32+mf*16+(lane>>2);
                int c=wn*32+nf*8+(lane&3)*2;
                float b0=b1b[c], b1v=b1b[c+1];
                float v00=fmaxf(acc[mf][nf][0]+b0,0.f), v01=fmaxf(acc[mf][nf][1]+b1v,0.f);
                float v10=fmaxf(acc[mf][nf][2]+b0,0.f), v11=fmaxf(acc[mf][nf][3]+b1v,0.f);
                __nv_bfloat16 h0,l0,h1,l1;
                splitf(v00,h0,l0); splitf(v01,h1,l1);
                __nv_bfloat162 hh,ll;
                hh.x=h0; hh.y=h1; ll.x=l0; ll.y=l1;
                *(__nv_bfloat162*)&AsH[r*S+c]=hh; *(__nv_bfloat162*)&AsL[r*S+c]=ll;
                splitf(v10,h0,l0); splitf(v11,h1,l1);
                hh.x=h0; hh.y=h1; ll.x=l0; ll.y=l1;
                *(__nv_bfloat162*)&AsH[(r+8)*S+c]=hh; *(__nv_bfloat162*)&AsL[(r+8)*S+c]=ll;
            }
        __syncthreads();

#pragma unroll
        for (int mf=0;mf<2;++mf)
#pragma unroll
            for (int nf=0;nf<8;++nf)
#pragma unroll
                for (int q=0;q<4;++q) acc[mf][nf][q]=0.f;
        mma_block<8,4,S>(acc, AsH, AsL, WcH, WcL, wm, wn*64, lane);

        const int cv0=cnt[cg0], cv1=cnt[cg0+1];
#pragma unroll
        for (int nf=0;nf<8;++nf){
            int c=wn*64+nf*8+(lane&3)*2;
            float b0=b1c[c], b1v=b1c[c+1];
            float m0=-FLT_MAX, m1=-FLT_MAX;
#pragma unroll
            for (int mf=0;mf<2;++mf){
                int r=wm*32+mf*16+(lane>>2);
                int cv=(r>>6)?cv1:cv0;
                int rl=r&63;
                if (rl   < cv){ m0=fmaxf(m0,acc[mf][nf][0]+b0); m1=fmaxf(m1,acc[mf][nf][1]+b1v); }
                if (rl+8 < cv){ m0=fmaxf(m0,acc[mf][nf][2]+b0); m1=fmaxf(m1,acc[mf][nf][3]+b1v); }
            }
#pragma unroll
            for (int off=4; off<32; off<<=1){
                m0=fmaxf(m0,__shfl_xor_sync(0xffffffffu,m0,off));
                m1=fmaxf(m1,__shfl_xor_sync(0xffffffffu,m1,off));
            }
            if (lane<4){ colmax[wid*128+c]=m0; colmax[wid*128+c+1]=m1; }
        }
        __syncthreads();
        {
            int cent=tid>>7, col=tid&127;
            int wb=(col>>6)*4 + cent*2;
            float m=fmaxf(colmax[wb*128+col], colmax[(wb+1)*128+col]);
            int cv = cent? cv1:cv0;
            float xv = cv? m : 0.f;
            x1[(size_t)(cg0+cent)*128+col] = xv;
            x1s[tid] = xv;
        }
        __syncthreads();
        {
            int cent=tid>>7, col=tid&127;
            const float* xr = x1s + cent*128;
            float s = w2as[16384+col];
            for (int k = 0; k < 128; ++k)
                s += xr[k]*w2as[k*128+col];
            y1[(size_t)(cg0+cent)*128+col] = s;
        }
    }
}

// ---- fused SA2 (R8) ----
__global__ void __launch_bounds__(256) sa2_fused_kernel(
    const float* __restrict__ y1, const float* __restrict__ pos1,
    const float* __restrict__ pos2, const int* __restrict__ nidx,
    const int* __restrict__ cnt, const float* __restrict__ W2a,
    const __nv_bfloat16* __restrict__ wbh, const __nv_bfloat16* __restrict__ wbl,
    const float* __restrict__ b2b,
    const __nv_bfloat16* __restrict__ wch, const __nv_bfloat16* __restrict__ wcl,
    const float* __restrict__ b2c,
    float* __restrict__ x2)
{
    constexpr int S = 136;
    extern __shared__ __align__(16) char sm2[];
    __nv_bfloat16* AsH = (__nv_bfloat16*)sm2;
    __nv_bfloat16* AsL = AsH + 128*S;
    __nv_bfloat16* WsH = AsL + 128*S;
    __nv_bfloat16* WsL = WsH + 128*S;
    float* w2a3  = (float*)(WsL + 128*S);
    float* colmax= w2a3 + 384;

    const int tid=threadIdx.x, lane=tid&31, wid=tid>>5;
    const int wm=wid&3, wn=wid>>2;
    const int cg0 = blockIdx.x*2;

    for (int t=tid; t<384; t+=256) w2a3[t]=W2a[16384+t];
    for (int t=tid; t<16384; t+=256){ int n=t>>7,k=t&127; WsH[n*S+k]=wbh[t]; WsL[n*S+k]=wbl[t]; }
    __syncthreads();

    {
        const int row=tid>>1, h0=(tid&1)*64;
        const int cg = cg0 + (row>>6);
        const int gp = (cg>>8)*M1C + nidx[cg*64 + (row&63)];
        const float rx = pos1[3*gp]  -pos2[3*cg];
        const float ry = pos1[3*gp+1]-pos2[3*cg+1];
        const float rz = pos1[3*gp+2]-pos2[3*cg+2];
        const float* yr = y1 + (size_t)gp*128;
#pragma unroll
        for (int j=0;j<64;++j){
            int n=h0+j;
            float v=fmaxf(yr[n]+rx*w2a3[n]+ry*w2a3[128+n]+rz*w2a3[256+n],0.f);
            splitf(v, AsH[row*S+n], AsL[row*S+n]);
        }
    }
    __syncthreads();

    float acc[2][8][4];
#pragma unroll
    for (int mf=0;mf<2;++mf)
#pragma unroll
        for (int nf=0;nf<8;++nf)
#pragma unroll
            for (int q=0;q<4;++q) acc[mf][nf][q]=0.f;
    mma_block<8,8,S>(acc, AsH, AsL, WsH, WsL, wm, wn*64, lane);
    __syncthreads();
#pragma unroll
    for (int mf=0;mf<2;++mf)
#pragma unroll
        for (int nf=0;nf<8;++nf){
            int r=wm*32+mf*16+(lane>>2);
            int c=wn*64+nf*8+(lane&3)*2;
            float b0=b2b[c], b1v=b2b[c+1];
            float v00=fmaxf(acc[mf][nf][0]+b0,0.f), v01=fmaxf(acc[mf][nf][1]+b1v,0.f);
            float v10=fmaxf(acc[mf][nf][2]+b0,0.f), v11=fmaxf(acc[mf][nf][3]+b1v,0.f);
            __nv_bfloat16 h0,l0,h1,l1;
            splitf(v00,h0,l0); splitf(v01,h1,l1);
            __nv_bfloat162 hh,ll;
            hh.x=h0; hh.y=h1; ll.x=l0; ll.y=l1;
            *(__nv_bfloat162*)&AsH[r*S+c]=hh; *(__nv_bfloat162*)&AsL[r*S+c]=ll;
            splitf(v10,h0,l0); splitf(v11,h1,l1);
            hh.x=h0; hh.y=h1; ll.x=l0; ll.y=l1;
            *(__nv_bfloat162*)&AsH[(r+8)*S+c]=hh; *(__nv_bfloat162*)&AsL[(r+8)*S+c]=ll;
        }

    const int cv0=cnt[cg0], cv1=cnt[cg0+1];
#pragma unroll
    for (int half=0; half<2; ++half){
        __syncthreads();
        for (int t=tid; t<16384; t+=256){
            int n=t>>7,k=t&127;
            WsH[n*S+k]=wch[half*16384+t]; WsL[n*S+k]=wcl[half*16384+t];
        }
        __syncthreads();
#pragma unroll
        for (int mf=0;mf<2;++mf)
#pragma unroll
            for (int nf=0;nf<8;++nf)
#pragma unroll
                for (int q=0;q<4;++q) acc[mf][nf][q]=0.f;
        mma_block<8,8,S>(acc, AsH, AsL, WsH, WsL, wm, wn*64, lane);
#pragma unroll
        for (int nf=0;nf<8;++nf){
            int c=wn*64+nf*8+(lane&3)*2;
            float b0=b2c[half*128+c], b1v=b2c[half*128+c+1];
            float m0=-FLT_MAX, m1=-FLT_MAX;
#pragma unroll
            for (int mf=0;mf<2;++mf){
                int r=wm*32+mf*16+(lane>>2);
                int cv=(r>>6)?cv1:cv0;
                int rl=r&63;
                if (rl   < cv){ m0=fmaxf(m0,acc[mf][nf][0]+b0); m1=fmaxf(m1,acc[mf][nf][1]+b1v); }
                if (rl+8 < cv){ m0=fmaxf(m0,acc[mf][nf][2]+b0); m1=fmaxf(m1,acc[mf][nf][3]+b1v); }
            }
#pragma unroll
            for (int off=4; off<32; off<<=1){
                m0=fmaxf(m0,__shfl_xor_sync(0xffffffffu,m0,off));
                m1=fmaxf(m1,__shfl_xor_sync(0xffffffffu,m1,off));
            }
            if (lane<4){ colmax[wid*128+c]=m0; colmax[wid*128+c+1]=m1; }
        }
        __syncthreads();
        {
            int cent=tid>>7, col=tid&127;
            int wb=(col>>6)*4 + cent*2;
            float m=fmaxf(colmax[wb*128+col], colmax[(wb+1)*128+col]);
            int cv = cent? cv1:cv0;
            x2[(size_t)(cg0+cent)*256 + half*128 + col] = cv? m : 0.f;
        }
    }
}

// ---- generic tensor-core GEMM: 128x64 tile, split bf16 ----
__global__ void __launch_bounds__(256) mma_gemm_kernel(
    const __nv_bfloat16* __restrict__ Ahi, const __nv_bfloat16* __restrict__ Alo,
    const __nv_bfloat16* __restrict__ Whi, const __nv_bfloat16* __restrict__ Wlo,
    const float* __restrict__ bias,
    float* __restrict__ outF,
    __nv_bfloat16* __restrict__ outHi, __nv_bfloat16* __restrict__ outLo,
    int N, int K, int relu)
{
    __shared__ __nv_bfloat16 AsH[128][34], AsL[128][34], WsH[64][34], WsL[64][34];
    const int tid = threadIdx.x;
    const int lane = tid & 31, wid = tid >> 5;
    const int wm = wid & 3, wn = wid >> 2;
    const int bm = blockIdx.y*128, bn = blockIdx.x*64;
    const int tcol = (tid & 15)*2, trow = tid >> 4;

    float acc[2][4][4];
#pragma unroll
    for (int mf=0; mf<2; ++mf)
#pragma unroll
        for (int nf=0; nf<4; ++nf)
#pragma unroll
            for (int q=0; q<4; ++q) acc[mf][nf][q]=0.f;

    for (int k0 = 0; k0 < K; k0 += 32) {
#pragma unroll
        for (int p = 0; p < 8; ++p) {
            int r = trow + p*16;
            size_t ga = (size_t)(bm + r)*K + k0 + tcol;
            *(unsigned*)&AsH[r][tcol] = *(const unsigned*)&Ahi[ga];
            *(unsigned*)&AsL[r][tcol] = *(const unsigned*)&Alo[ga];
        }
#pragma unroll
        for (int p = 0; p < 4; ++p) {
            int n = trow + p*16;
            size_t gw = (size_t)(bn + n)*K + k0 + tcol;
            *(unsigned*)&WsH[n][tcol] = *(const unsigned*)&Whi[gw];
            *(unsigned*)&WsL[n][tcol] = *(const unsigned*)&Wlo[gw];
        }
        __syncthreads();
#pragma unroll
        for (int ks = 0; ks < 2; ++ks) {
            const int kk = ks*16 + (lane&3)*2;
            unsigned ah[2][4], al[2][4], bh[4][2], bl[4][2];
#pragma unroll
            for (int mf=0; mf<2; ++mf) {
                int r = wm*32 + mf*16 + (lane>>2);
                ah[mf][0]=*(const unsigned*)&AsH[r][kk];
                ah[mf][1]=*(const unsigned*)&AsH[r+8][kk];
                ah[mf][2]=*(const unsigned*)&AsH[r][kk+8];
                ah[mf][3]=*(const unsigned*)&AsH[r+8][kk+8];
                al[mf][0]=*(const unsigned*)&AsL[r][kk];
                al[mf][1]=*(const unsigned*)&AsL[r+8][kk];
                al[mf][2]=*(const unsigned*)&AsL[r][kk+8];
                al[mf][3]=*(const unsigned*)&AsL[r+8][kk+8];
            }
#pragma unroll
            for (int nf=0; nf<4; ++nf) {
                int n = wn*32 + nf*8 + (lane>>2);
                bh[nf][0]=*(const unsigned*)&WsH[n][kk];
                bh[nf][1]=*(const unsigned*)&WsH[n][kk+8];
                bl[nf][0]=*(const unsigned*)&WsL[n][kk];
                bl[nf][1]=*(const unsigned*)&WsL[n][kk+8];
            }
#pragma unroll
            for (int mf=0; mf<2; ++mf)
#pragma unroll
                for (int nf=0; nf<4; ++nf) {
                    mma16816(acc[mf][nf], ah[mf], bh[nf]);
                    mma16816(acc[mf][nf], ah[mf], bl[nf]);
                    mma16816(acc[mf][nf], al[mf], bh[nf]);
                }
        }
        __syncthreads();
    }

#pragma unroll
    for (int mf=0; mf<2; ++mf)
#pragma unroll
        for (int nf=0; nf<4; ++nf) {
            int r = bm + wm*32 + mf*16 + (lane>>2);
            int c = bn + wn*32 + nf*8 + (lane&3)*2;
            float b0 = bias[c], b1 = bias[c+1];
            float v00 = acc[mf][nf][0]+b0, v01 = acc[mf][nf][1]+b1;
            float v10 = acc[mf][nf][2]+b0, v11 = acc[mf][nf][3]+b1;
            if (relu) {
                v00=fmaxf(v00,0.f); v01=fmaxf(v01,0.f);
                v10=fmaxf(v10,0.f); v11=fmaxf(v11,0.f);
            }
            if (outF) {
                outF[(size_t)r*N + c]   = v00; outF[(size_t)r*N + c+1]   = v01;
                outF[(size_t)(r+8)*N+c] = v10; outF[(size_t)(r+8)*N+c+1] = v11;
            }
            if (outHi) {
                __nv_bfloat16 h0,l0,h1,l1;
                splitf(v00,h0,l0); splitf(v01,h1,l1);
                __nv_bfloat162 hh; hh.x=h0; hh.y=h1;
                __nv_bfloat162 ll; ll.x=l0; ll.y=l1;
                *(__nv_bfloat162*)&outHi[(size_t)r*N + c] = hh;
                *(__nv_bfloat162*)&outLo[(size_t)r*N + c] = ll;
                splitf(v10,h0,l0); splitf(v11,h1,l1);
                hh.x=h0; hh.y=h1; ll.x=l0; ll.y=l1;
                *(__nv_bfloat162*)&outHi[(size_t)(r+8)*N + c] = hh;
                *(__nv_bfloat162*)&outLo[(size_t)(r+8)*N + c] = ll;
            }
        }
}

// ---- SA3 feature build ----
__global__ void feats3_split_kernel(const float* __restrict__ x2, const float* __restrict__ pos2,
                                    __nv_bfloat16* __restrict__ hi, __nv_bfloat16* __restrict__ lo)
{
    int row = blockIdx.x*2 + (threadIdx.x>>7);
    int c0 = threadIdx.x & 127;
    for (int c = c0; c < 288; c += 128) {
        float v = (c < 256) ? x2[(size_t)row*256 + c]
                : (c < 259) ? pos2[row*3 + c - 256] : 0.f;
        splitf(v, hi[(size_t)row*288 + c], lo[(size_t)row*288 + c]);
    }
}

__global__ void pool256_kernel(const float* __restrict__ g, float* __restrict__ gfeat)
{
    int b = blockIdx.y, f = blockIdx.x*256 + threadIdx.x;
    float m = -FLT_MAX;
    for (int r = 0; r < M2C; ++r)
        m = fmaxf(m, g[(size_t)(b*M2C+r)*1024 + f]);
    gfeat[b*1024+f]=m;
}

__global__ void head_kernel(const float* __restrict__ gfeat,
                            const float* __restrict__ Wh1, const float* __restrict__ bh1,
                            const float* __restrict__ Wh2, const float* __restrict__ bh2,
                            const float* __restrict__ Wh3, const float* __restrict__ bh3,
                            float* __restrict__ out)
{
    __shared__ float gf[1024], h1[512], h2[256], lg[10];
    const int b=blockIdx.x, tid=threadIdx.x;
    for (int i = tid; i < 1024; i += 256) gf[i]=gfeat[b*1024+i];
    __syncthreads();
    for (int n = tid; n < 512; n += 256) {
        float s = bh1[n];
        for (int k = 0; k < 1024; ++k) s += gf[k]*Wh1[(size_t)k*512+n];
        h1[n]=fmaxf(s,0.f);
    }
    __syncthreads();
    { float s = bh2[tid];
      for (int k = 0; k < 512; ++k) s += h1[k]*Wh2[(size_t)k*256+tid];
      h2[tid]=fmaxf(s,0.f); }
    __syncthreads();
    if (tid < 10) {
        float s = bh3[tid];
        for (int k = 0; k < 256; ++k) s += h2[k]*Wh3[k*10+tid];
        lg[tid]=s;
    }
    __syncthreads();
    if (tid == 0) {
        float m=lg[0];
        for (int j=1;j<10;++j) m=fmaxf(m,lg[j]);
        float se=0.f;
        for (int j=0;j<10;++j) se+=expf(lg[j]-m);
        float l=logf(se);
        for (int j=0;j<10;++j) out[b*10+j]=lg[j]-m-l;
    }
}

extern "C" void kernel_launch(void* const* d_in, const int* in_sizes, int n_in,
                              void* d_out, int out_size)
{
    const float* pos=(const float*)d_in[0];
    const float *W1a=(const float*)d_in[1],  *b1a=(const float*)d_in[2];
    const float *W1b=(const float*)d_in[3],  *b1b=(const float*)d_in[4];
    const float *W1c=(const float*)d_in[5],  *b1c=(const float*)d_in[6];
    const float *W2a=(const float*)d_in[7],  *b2a=(const float*)d_in[8];
    const float *W2b=(const float*)d_in[9],  *b2b=(const float*)d_in[10];
    const float *W2c=(const float*)d_in[11], *b2c=(const float*)d_in[12];
    const float *W3a=(const float*)d_in[13], *b3a=(const float*)d_in[14];
    const float *W3b=(const float*)d_in[15], *b3b=(const float*)d_in[16];
    const float *W3c=(const float*)d_in[17], *b3c=(const float*)d_in[18];
    const float *Wh1=(const float*)d_in[19], *bh1=(const float*)d_in[20];
    const float *Wh2=(const float*)d_in[21], *bh2=(const float*)d_in[22];
    const float *Wh3=(const float*)d_in[23], *bh3=(const float*)d_in[24];

    float *curv,*pos1,*curv1,*pos2,*x1,*x2,*gfeat,*fF,*bA;
    int *nidx1,*cnt1,*nidx2,*cnt2;
    __nv_bfloat16 *w1bh,*w1bl,*w1ch,*w1cl,*w2bh,*w2bl,*w2ch,*w2cl;
    __nv_bfloat16 *w3ah,*w3al,*w3bh,*w3bl,*w3ch,*w3cl;
    __nv_bfloat16 *pAh,*pAl,*pBh,*pBl,*pCh,*pCl;
    cudaGetSymbolAddress((void**)&curv, g_curv);
    cudaGetSymbolAddress((void**)&pos1, g_pos1);
    cudaGetSymbolAddress((void**)&curv1,g_curv1);
    cudaGetSymbolAddress((void**)&pos2, g_pos2);
    cudaGetSymbolAddress((void**)&nidx1,g_nidx1);
    cudaGetSymbolAddress((void**)&cnt1, g_cnt1);
    cudaGetSymbolAddress((void**)&nidx2,g_nidx2);
    cudaGetSymbolAddress((void**)&cnt2, g_cnt2);
    cudaGetSymbolAddress((void**)&x1,   g_x1);
    cudaGetSymbolAddress((void**)&x2,   g_x2);
    cudaGetSymbolAddress((void**)&gfeat,g_gfeat);
    cudaGetSymbolAddress((void**)&fF,   g_featF);
    cudaGetSymbolAddress((void**)&bA,   g_bufA);
    cudaGetSymbolAddress((void**)&w1bh, g_w1bh); cudaGetSymbolAddress((void**)&w1bl, g_w1bl);
    cudaGetSymbolAddress((void**)&w1ch, g_w1ch); cudaGetSymbolAddress((void**)&w1cl, g_w1cl);
    cudaGetSymbolAddress((void**)&w2bh, g_w2bh); cudaGetSymbolAddress((void**)&w2bl, g_w2bl);
    cudaGetSymbolAddress((void**)&w2ch, g_w2ch); cudaGetSymbolAddress((void**)&w2cl, g_w2cl);
    cudaGetSymbolAddress((void**)&w3ah, g_w3ah); cudaGetSymbolAddress((void**)&w3al, g_w3al);
    cudaGetSymbolAddress((void**)&w3bh, g_w3bh); cudaGetSymbolAddress((void**)&w3bl, g_w3bl);
    cudaGetSymbolAddress((void**)&w3ch, g_w3ch); cudaGetSymbolAddress((void**)&w3cl, g_w3cl);
    cudaGetSymbolAddress((void**)&pAh,  g_pAh);  cudaGetSymbolAddress((void**)&pAl,  g_pAl);
    cudaGetSymbolAddress((void**)&pBh,  g_pBh);  cudaGetSymbolAddress((void**)&pBl,  g_pBl);
    cudaGetSymbolAddress((void**)&pCh,  g_pCh);  cudaGetSymbolAddress((void**)&pCl,  g_pCl);

    cudaFuncSetAttribute(sa1_fused_kernel, cudaFuncAttributeMaxDynamicSharedMemorySize, 164352);
    cudaFuncSetAttribute(sa2_fused_kernel, cudaFuncAttributeMaxDynamicSharedMemorySize, 144896);

    cudaStream_t s2; cudaStreamCreateWithFlags(&s2, cudaStreamNonBlocking);
    cudaEvent_t e0, eW, e1, e2;
    cudaEventCreateWithFlags(&e0, cudaEventDisableTiming);
    cudaEventCreateWithFlags(&eW, cudaEventDisableTiming);
    cudaEventCreateWithFlags(&e1, cudaEventDisableTiming);
    cudaEventCreateWithFlags(&e2, cudaEventDisableTiming);

    // weight preps on s2 (R8 structure)
    cudaEventRecord(e0, 0);
    cudaStreamWaitEvent(s2, e0, 0);
    wprep_kernel<<<16, 256, 0, s2>>>(W1b, w1bh, w1bl, 64, 64);
    wprep_kernel<<<32, 256, 0, s2>>>(W1c, w1ch, w1cl, 64, 128);
    wprep_kernel<<<64, 256, 0, s2>>>(W2b, w2bh, w2bl, 128, 128);
    wprep_kernel<<<128,256, 0, s2>>>(W2c, w2ch, w2cl, 128, 256);
    wprep_pad_kernel<<<288, 256, 0, s2>>>(W3a, w3ah, w3al, 259, 256, 288);
    wprep_kernel<<<512, 256, 0, s2>>>(W3b, w3bh, w3bl, 256, 512);
    wprep_kernel<<<2048,256, 0, s2>>>(W3c, w3ch, w3cl, 512, 1024);
    cudaEventRecord(eW, s2);

    // curvature + FPS1 (fused gather -> pos1/curv1)
    curvature_kernel<<<BATCH*(NPT/128), 128>>>(pos, curv);
    fps_kernel<NPT,M1C><<<BATCH, 256>>>(pos, curv, pos1, curv1);
    cudaEventRecord(e1, 0);

    // branch B on s2: FPS2 + group2
    cudaStreamWaitEvent(s2, e1, 0);
    fps_kernel<M1C,M2C><<<BATCH, 256, 0, s2>>>(pos1, curv1, pos2, (float*)0);
    group_kernel<M1C,512,4><<<dim3(M2C/4, BATCH), 128, 0, s2>>>(pos1, pos2, nidx2, cnt2, M2C, 0.16f);
    cudaEventRecord(e2, s2);

    // branch A on main: group1 + SA1 (writes x1 AND y1)
    group_kernel<NPT,128,8><<<dim3(M1C/8, BATCH), 256>>>(pos, pos1, nidx1, cnt1, M1C, 0.04f);
    cudaStreamWaitEvent(0, eW, 0);
    sa1_fused_kernel<<<152, 256, 164352>>>(pos, pos1, nidx1, cnt1,
        W1a, b1a, w1bh, w1bl, b1b, w1ch, w1cl, b1c, W2a, b2a, x1, fF);

    // join, SA2
    cudaStreamWaitEvent(0, e2, 0);
    sa2_fused_kernel<<<BATCH*M2C/2, 256, 144896>>>(fF, pos1, pos2, nidx2, cnt2,
        W2a, w2bh, w2bl, b2b, w2ch, w2cl, b2c, x2);

    // SA3 on tensor cores
    feats3_split_kernel<<<BATCH*M2C/2, 256>>>(x2, pos2, pAh, pAl);
    mma_gemm_kernel<<<dim3(4, 16), 256>>>(pAh, pAl, w3ah, w3al, b3a,
                                          (float*)0, pBh, pBl, 256, 288, 1);
    mma_gemm_kernel<<<dim3(8, 16), 256>>>(pBh, pBl, w3bh, w3bl, b3b,
                                          (float*)0, pCh, pCl, 512, 256, 1);
    mma_gemm_kernel<<<dim3(16, 16), 256>>>(pCh, pCl, w3ch, w3cl, b3c,
                                           bA, (__nv_bfloat16*)0, (__nv_bfloat16*)0, 1024, 512, 0);
    pool256_kernel<<<dim3(4, BATCH), 256>>>(bA, gfeat);

    // head
    head_kernel<<<BATCH, 256>>>(gfeat, Wh1, bh1, Wh2, bh2, Wh3, bh3, (float*)d_out);
}

// round 15
// speedup vs baseline: 1.2776x; 1.0623x over previous
#include <cuda_runtime.h>
#include <cuda_bf16.h>
#include <math.h>
#include <float.h>

#define BATCH 8
#define NPT   2048
#define M1C   1024
#define M2C   256
#define KNB   64
#define CURVK 10

// ---- scratch (device globals; no allocation) ----
__device__ float g_curv [BATCH*NPT];
__device__ float g_pos1 [BATCH*M1C*3];
__device__ float g_curv1[BATCH*M1C];
__device__ float g_pos2 [BATCH*M2C*3];
__device__ int   g_nidx1[BATCH*M1C*KNB];
__device__ int   g_cnt1 [BATCH*M1C];
__device__ int   g_nidx2[BATCH*M2C*KNB];
__device__ int   g_cnt2 [BATCH*M2C];
__device__ float g_x1   [BATCH*M1C*128];
__device__ float g_x2   [BATCH*M2C*256];
__device__ float g_gfeat[BATCH*1024];
__device__ float g_featF[1024*1024];          // y1 (8192x128)
__device__ float g_bufA [2*1024*1024];        // SA3 final fp32 (2048x1024)
__device__ __nv_bfloat16 g_w1bh[4096],  g_w1bl[4096];
__device__ __nv_bfloat16 g_w1ch[8192],  g_w1cl[8192];
__device__ __nv_bfloat16 g_w2bh[16384], g_w2bl[16384];
__device__ __nv_bfloat16 g_w2ch[32768], g_w2cl[32768];
__device__ __nv_bfloat16 g_w3ah[73728], g_w3al[73728];
__device__ __nv_bfloat16 g_w3bh[131072],g_w3bl[131072];
__device__ __nv_bfloat16 g_w3ch[524288],g_w3cl[524288];
__device__ __nv_bfloat16 g_pAh[589824], g_pAl[589824];
__device__ __nv_bfloat16 g_pBh[524288], g_pBl[524288];
__device__ __nv_bfloat16 g_pCh[1048576],g_pCl[1048576];

__device__ __forceinline__ void splitf(float v, __nv_bfloat16& h, __nv_bfloat16& l) {
    h = __float2bfloat16(v);
    l = __float2bfloat16(v - __bfloat162float(h));
}

__device__ __forceinline__ void mma16816(float* c, const unsigned* a, const unsigned* b) {
    asm volatile(
      "mma.sync.aligned.m16n8k16.row.col.f32.bf16.bf16.f32 "
      "{%0,%1,%2,%3}, {%4,%5,%6,%7}, {%8,%9}, {%0,%1,%2,%3};\n"
      : "+f"(c[0]), "+f"(c[1]), "+f"(c[2]), "+f"(c[3])
      : "r"(a[0]), "r"(a[1]), "r"(a[2]), "r"(a[3]), "r"(b[0]), "r"(b[1]));
}

template<int NF,int K16,int S>
__device__ __forceinline__ void mma_block(
    float (&acc)[2][8][4],
    const __nv_bfloat16* AsH, const __nv_bfloat16* AsL,
    const __nv_bfloat16* WH,  const __nv_bfloat16* WL,
    int wm, int wnbase, int lane)
{
#pragma unroll
    for (int k16=0;k16<K16;++k16){
        const int kk=k16*16+(lane&3)*2;
        unsigned ah[2][4], al[2][4];
#pragma unroll
        for (int mf=0;mf<2;++mf){
            int r=wm*32+mf*16+(lane>>2);
            ah[mf][0]=*(const unsigned*)&AsH[r*S+kk];
            ah[mf][1]=*(const unsigned*)&AsH[(r+8)*S+kk];
            ah[mf][2]=*(const unsigned*)&AsH[r*S+kk+8];
            ah[mf][3]=*(const unsigned*)&AsH[(r+8)*S+kk+8];
            al[mf][0]=*(const unsigned*)&AsL[r*S+kk];
            al[mf][1]=*(const unsigned*)&AsL[(r+8)*S+kk];
            al[mf][2]=*(const unsigned*)&AsL[r*S+kk+8];
            al[mf][3]=*(const unsigned*)&AsL[(r+8)*S+kk+8];
        }
#pragma unroll
        for (int nf=0;nf<NF;++nf){
            int n=wnbase+nf*8+(lane>>2);
            unsigned bh[2]={*(const unsigned*)&WH[n*S+kk], *(const unsigned*)&WH[n*S+kk+8]};
            unsigned bl[2]={*(const unsigned*)&WL[n*S+kk], *(const unsigned*)&WL[n*S+kk+8]};
#pragma unroll
            for (int mf=0;mf<2;++mf){
                mma16816(acc[mf][nf], ah[mf], bh);
                mma16816(acc[mf][nf], ah[mf], bl);
                mma16816(acc[mf][nf], al[mf], bh);
            }
        }
    }
}

// ---- curvature: 2 threads per query, half-scans merged (bitwise-identical sets) ----
__global__ void __launch_bounds__(256) curvature_kernel(const float* __restrict__ pos,
                                                        float* __restrict__ curv)
{
    __shared__ float px[NPT], py[NPT], pz[NPT], nr[NPT];
    __shared__ float sd[256*CURVK];
    __shared__ int   si[256*CURVK];
    const int b = blockIdx.x / (NPT/128);
    const int tid = threadIdx.x;
    const float* cp = pos + (size_t)b * NPT * 3;
    for (int i = tid; i < NPT; i += 256) {
        float x = cp[3*i], y = cp[3*i+1], z = cp[3*i+2];
        px[i]=x; py[i]=y; pz[i]=z; nr[i]=x*x+y*y+z*z;
    }
    __syncthreads();
    const int q = (blockIdx.x % (NPT/128)) * 128 + (tid & 127);
    const int half = tid >> 7;
    const int jlo = half*1024, jhi = jlo+1024;
    const float qx=px[q], qy=py[q], qz=pz[q], nq=nr[q];

    float td[CURVK]; int ti[CURVK];
#pragma unroll
    for (int s = 0; s < CURVK; ++s) { td[s]=3.4e38f; ti[s]=0; }
#pragma unroll 8
    for (int j = jlo; j < jhi; ++j) {
        float d2 = nq + nr[j] - 2.0f*(qx*px[j]+qy*py[j]+qz*pz[j]);
        if (d2 < td[CURVK-1]) {
            float cd=d2; int ci=j;
#pragma unroll
            for (int s = 0; s < CURVK; ++s)
                if (cd < td[s]) { float t=td[s]; td[s]=cd; cd=t; int u=ti[s]; ti[s]=ci; ci=u; }
        }
    }
#pragma unroll
    for (int s = 0; s < CURVK; ++s) { sd[tid*CURVK+s]=td[s]; si[tid*CURVK+s]=ti[s]; }
    __syncthreads();
    if (half) return;

    // merge own (left, lower indices) with partner (right) — ties prefer left
    float md_[CURVK]; int mi_[CURVK];
    {
        const float* ld = &sd[tid*CURVK];        const int* li = &si[tid*CURVK];
        const float* rd = &sd[(tid+128)*CURVK];  const int* ri = &si[(tid+128)*CURVK];
        int a=0, c=0;
#pragma unroll
        for (int s = 0; s < CURVK; ++s) {
            float dl = ld[a], dr = rd[c];
            if (dl <= dr) { md_[s]=dl; mi_[s]=li[a]; ++a; }
            else          { md_[s]=dr; mi_[s]=ri[c]; ++c; }
        }
    }

    float mx=0,my=0,mz=0;
#pragma unroll
    for (int s = 0; s < CURVK; ++s) { mx+=px[mi_[s]]; my+=py[mi_[s]]; mz+=pz[mi_[s]]; }
    mx/=CURVK; my/=CURVK; mz/=CURVK;
    double cxx=0,cxy=0,cxz=0,cyy=0,cyz=0,czz=0;
#pragma unroll
    for (int s = 0; s < CURVK; ++s) {
        float ax=px[mi_[s]]-mx, ay=py[mi_[s]]-my, az=pz[mi_[s]]-mz;
        cxx+=(double)ax*ax; cxy+=(double)ax*ay; cxz+=(double)ax*az;
        cyy+=(double)ay*ay; cyz+=(double)ay*az; czz+=(double)az*az;
    }
    cxx/=CURVK; cxy/=CURVK; cxz/=CURVK; cyy/=CURVK; cyz/=CURVK; czz/=CURVK;
    double tr=cxx+cyy+czz;
    double p1=cxy*cxy+cxz*cxz+cyz*cyz;
    double qv=tr/3.0;
    double p2=(cxx-qv)*(cxx-qv)+(cyy-qv)*(cyy-qv)+(czz-qv)*(czz-qv)+2.0*p1;
    double lmin;
    if (p2 < 1e-32) lmin = qv;
    else {
        double p=sqrt(p2/6.0);
        double b00=(cxx-qv)/p,b11=(cyy-qv)/p,b22=(czz-qv)/p,b01=cxy/p,b02=cxz/p,b12=cyz/p;
        double detB=b00*(b11*b22-b12*b12)-b01*(b01*b22-b12*b02)+b02*(b01*b12-b11*b02);
        double r=fmin(1.0,fmax(-1.0,detB*0.5));
        lmin=qv+2.0*p*cos(acos(r)/3.0 + 2.0943951023931953);
    }
    curv[b*NPT+q]=(float)(lmin/(tr+1e-8));
}

// ---- weighted FPS with fused gather (R8 body, 256 thr) ----
template<int NPTS,int MOUT>
__global__ void __launch_bounds__(256) fps_kernel(const float* __restrict__ pos,
                                                  const float* __restrict__ curv,
                                                  float* __restrict__ opos,
                                                  float* __restrict__ ocurv)
{
    constexpr int THR=256, E=NPTS/THR, NW=8;
    __shared__ float spx[NPTS], spy[NPTS], spz[NPTS], scv[NPTS];
    __shared__ unsigned long long wkey[2][NW];
    const int b=blockIdx.x, tid=threadIdx.x, lane=tid&31, wid=tid>>5;
    const float* cp = pos + (size_t)b*NPTS*3;
    float px[E],py[E],pz[E],ww[E],md[E];
#pragma unroll
    for (int e=0;e<E;++e){
        int i=tid+e*THR;
        float x=cp[3*i], y=cp[3*i+1], z=cp[3*i+2];
        float cv=curv[b*NPTS+i];
        px[e]=x; py[e]=y; pz[e]=z;
        spx[i]=x; spy[i]=y; spz[i]=z; scv[i]=cv;
        ww[e]=1.0f+10.0f*cv;
        md[e]=FLT_MAX;
    }
    __syncthreads();
    float sx=spx[0], sy=spy[0], sz=spz[0];
    if (tid==0){
        int o=b*MOUT;
        opos[3*o]=sx; opos[3*o+1]=sy; opos[3*o+2]=sz;
        if (ocurv) ocurv[o]=scv[0];
    }
    for (int m=1;m<MOUT;++m){
        float bv=-1.f; int bi=0;
#pragma unroll
        for (int e=0;e<E;++e){
            int i=tid+e*THR;
            float dx=px[e]-sx, dy=py[e]-sy, dz=pz[e]-sz;
            float d=fminf(md[e], dx*dx+dy*dy+dz*dz);
            md[e]=d;
            float v=d*ww[e];
            if (v>bv){ bv=v; bi=i; }   // i increasing per thread -> first max kept
        }
        unsigned hv=__float_as_uint(bv);
        unsigned hm=__reduce_max_sync(0xffffffffu, hv);
        unsigned lm=__reduce_max_sync(0xffffffffu, (hv==hm)? ~(unsigned)bi : 0u);
        if (lane==0) wkey[m&1][wid]=((unsigned long long)hm<<32)|lm;
        __syncthreads();
        unsigned long long k2 = (lane<NW)? wkey[m&1][lane] : 0ull;
        unsigned h2=(unsigned)(k2>>32), l2=(unsigned)k2;
        unsigned hm2=__reduce_max_sync(0xffffffffu, h2);
        unsigned lm2=__reduce_max_sync(0xffffffffu, (h2==hm2)? l2 : 0u);
        int s=(int)(~lm2);
        sx=spx[s]; sy=spy[s]; sz=spz[s];
        if (tid==0){
            int o=b*MOUT+m;
            opos[3*o]=sx; opos[3*o+1]=sy; opos[3*o+2]=sz;
            if (ocurv) ocurv[o]=scv[s];
        }
    }
}

// ---- radius grouping (R8 config) ----
template<int NPTS,int CAP,int CPB>
__global__ void group_kernel(const float* __restrict__ pts, const float* __restrict__ cents,
                             int* __restrict__ nidx, int* __restrict__ cnt_out,
                             int MC, float r2)
{
    __shared__ float px[NPTS],py[NPTS],pz[NPTS],nr[NPTS];
    __shared__ unsigned long long cand[CPB][CAP];
    const int b=blockIdx.y, tid=threadIdx.x;
    const float* cp = pts + (size_t)b*NPTS*3;
    for (int i = tid; i < NPTS; i += CPB*32) {
        float x=cp[3*i],y=cp[3*i+1],z=cp[3*i+2];
        px[i]=x; py[i]=y; pz[i]=z; nr[i]=x*x+y*y+z*z;
    }
    __syncthreads();
    const int w=tid>>5, lane=tid&31;
    const int c=blockIdx.x*CPB+w, cg=b*MC+c;
    const float cx=cents[3*cg],cy=cents[3*cg+1],cz=cents[3*cg+2];
    const float nc=cx*cx+cy*cy+cz*cz;
    int cnt=0;
    for (int j0 = 0; j0 < NPTS; j0 += 32) {
        int j=j0+lane;
        float d2 = nc + nr[j] - 2.0f*(cx*px[j]+cy*py[j]+cz*pz[j]);
        bool in = (d2 <= r2);
        unsigned mask = __ballot_sync(0xffffffffu, in);
        if (in) {
            int p = cnt + __popc(mask & ((1u<<lane)-1u));
            if (p < CAP) {
                unsigned ub=__float_as_uint(d2);
                ub = (ub&0x80000000u) ? ~ub : (ub|0x80000000u);
                cand[w][p] = ((unsigned long long)ub<<32) | (unsigned)j;
            }
        }
        cnt += __popc(mask);
    }
    if (cnt > CAP) cnt = CAP;
    for (int i = cnt+lane; i < CAP; i += 32) cand[w][i]=0xFFFFFFFFFFFFFFFFull;
    __syncwarp();
    for (int k = 2; k <= CAP; k <<= 1)
        for (int j = k>>1; j > 0; j >>= 1) {
            for (int i = lane; i < CAP; i += 32) {
                int ixj = i^j;
                if (ixj > i) {
                    unsigned long long a=cand[w][i], bb=cand[w][ixj];
                    if ((a>bb) == ((i&k)==0)) { cand[w][i]=bb; cand[w][ixj]=a; }
                }
            }
            __syncwarp();
        }
    int nv = cnt < KNB ? cnt : KNB;
    int fb = (nv>0) ? (int)(cand[w][0]&0xffffffffu) : 0;
    for (int i = lane; i < KNB; i += 32)
        nidx[(size_t)cg*KNB+i] = (i<nv) ? (int)(cand[w][i]&0xffffffffu) : fb;
    if (lane==0) cnt_out[cg]=nv;
}

// ---- weight prep (R8: separate kernels) ----
__global__ void wprep_kernel(const float* __restrict__ W,
                             __nv_bfloat16* __restrict__ hi, __nv_bfloat16* __restrict__ lo,
                             int K, int N)
{
    int t = blockIdx.x*256 + threadIdx.x;
    if (t >= K*N) return;
    int n = t / K, k = t % K;
    __nv_bfloat16 h,l; splitf(W[(size_t)k*N + n], h, l);
    hi[t]=h; lo[t]=l;
}
__global__ void wprep_pad_kernel(const float* __restrict__ W,
                                 __nv_bfloat16* __restrict__ hi, __nv_bfloat16* __restrict__ lo,
                                 int K, int N, int Kpad)
{
    int t = blockIdx.x*256 + threadIdx.x;
    if (t >= N*Kpad) return;
    int n = t / Kpad, k = t % Kpad;
    float v = (k < K) ? W[(size_t)k*N + n] : 0.f;
    __nv_bfloat16 h,l; splitf(v, h, l);
    hi[t]=h; lo[t]=l;
}

// ---- fused SA1 (persistent, grid 152) + y1 epilogue (R8) ----
__global__ void __launch_bounds__(256) sa1_fused_kernel(
    const float* __restrict__ pos, const float* __restrict__ pos1,
    const int* __restrict__ nidx, const int* __restrict__ cnt,
    const float* __restrict__ W1a, const float* __restrict__ b1a,
    const __nv_bfloat16* __restrict__ wbh, const __nv_bfloat16* __restrict__ wbl,
    const float* __restrict__ b1b,
    const __nv_bfloat16* __restrict__ wch, const __nv_bfloat16* __restrict__ wcl,
    const float* __restrict__ b1c,
    const float* __restrict__ W2a, const float* __restrict__ b2a,
    float* __restrict__ x1, float* __restrict__ y1)
{
    constexpr int S = 72;
    extern __shared__ __align__(16) char sm1[];
    __nv_bfloat16* AsH = (__nv_bfloat16*)sm1;
    __nv_bfloat16* AsL = AsH + 128*S;
    __nv_bfloat16* WcH = AsL + 128*S;
    __nv_bfloat16* WcL = WcH + 128*S;
    __nv_bfloat16* WbH = WcL + 128*S;
    __nv_bfloat16* WbL = WbH + 64*S;
    float* w1s   = (float*)(WbL + 64*S);
    float* colmax= w1s + 256;
    float* x1s   = colmax + 1024;
    float* w2as  = x1s + 256;

    const int tid=threadIdx.x, lane=tid&31, wid=tid>>5;
    const int wm=wid&3, wn=wid>>2;

    for (int t=tid; t<64*64;  t+=256){ int n=t>>6,k=t&63; WbH[n*S+k]=wbh[t]; WbL[n*S+k]=wbl[t]; }
    for (int t=tid; t<128*64; t+=256){ int n=t>>6,k=t&63; WcH[n*S+k]=wch[t]; WcL[n*S+k]=wcl[t]; }
    for (int t=tid; t<16384; t+=256) w2as[t]=W2a[t];
    if (tid<128) w2as[16384+tid]=b2a[tid];
    if (tid<192) w1s[tid]=W1a[tid];
    else if (tid<256) w1s[tid]=b1a[tid-192];

    const int NT = BATCH*M1C/2;
    for (int tile = blockIdx.x; tile < NT; tile += gridDim.x) {
        const int cg0 = tile*2;
        __syncthreads();
        {
            const int row=tid>>1, h0=(tid&1)*32;
            const int cg = cg0 + (row>>6);
            const int p  = nidx[cg*64 + (row&63)];
            const int src = (cg>>10)*NPT + p;
            const float rx = pos[3*src]  -pos1[3*cg];
            const float ry = pos[3*src+1]-pos1[3*cg+1];
            const float rz = pos[3*src+2]-pos1[3*cg+2];
#pragma unroll
            for (int j=0;j<32;++j){
                int n=h0+j;
                float v=fmaxf(rx*w1s[n]+ry*w1s[64+n]+rz*w1s[128+n]+w1s[192+n],0.f);
                splitf(v, AsH[row*S+n], AsL[row*S+n]);
            }
        }
        __syncthreads();

        float acc[2][8][4];
#pragma unroll
        for (int mf=0;mf<2;++mf)
#pragma unroll
            for (int nf=0;nf<4;++nf)
#pragma unroll
                for (int q=0;q<4;++q) acc[mf][nf][q]=0.f;
        mma_block<4,4,S>(acc, AsH, AsL, WbH, WbL, wm, wn*32, lane);
        __syncthreads();
#pragma unroll
        for (int mf=0;mf<2;++mf)
#pragma unroll
            for (int nf=0;nf<4;++nf){
                int r=wm*32+mf*16+(lane>>2);
                int c=wn*32+nf*8+(lane&3)*2;
                float b0=b1b[c], b1v=b1b[c+1];
                float v00=fmaxf(acc[mf][nf][0]+b0,0.f), v01=fmaxf(acc[mf][nf][1]+b1v,0.f);
                float v10=fmaxf(acc[mf][nf][2]+b0,0.f), v11=fmaxf(acc[mf][nf][3]+b1v,0.f);
                __nv_bfloat16 h0,l0,h1,l1;
                splitf(v00,h0,l0); splitf(v01,h1,l1);
                __nv_bfloat162 hh,ll;
                hh.x=h0; hh.y=h1; ll.x=l0; ll.y=l1;
                *(__nv_bfloat162*)&AsH[r*S+c]=hh; *(__nv_bfloat162*)&AsL[r*S+c]=ll;
                splitf(v10,h0,l0); splitf(v11,h1,l1);
                hh.x=h0; hh.y=h1; ll.x=l0; ll.y=l1;
                *(__nv_bfloat162*)&AsH[(r+8)*S+c]=hh; *(__nv_bfloat162*)&AsL[(r+8)*S+c]=ll;
            }
        __syncthreads();

#pragma unroll
        for (int mf=0;mf<2;++mf)
#pragma unroll
            for (int nf=0;nf<8;++nf)
#pragma unroll
                for (int q=0;q<4;++q) acc[mf][nf][q]=0.f;
        mma_block<8,4,S>(acc, AsH, AsL, WcH, WcL, wm, wn*64, lane);

        const int cv0=cnt[cg0], cv1=cnt[cg0+1];
#pragma unroll
        for (int nf=0;nf<8;++nf){
            int c=wn*64+nf*8+(lane&3)*2;
            float b0=b1c[c], b1v=b1c[c+1];
            float m0=-FLT_MAX, m1=-FLT_MAX;
#pragma unroll
            for (int mf=0;mf<2;++mf){
                int r=wm*32+mf*16+(lane>>2);
                int cv=(r>>6)?cv1:cv0;
                int rl=r&63;
                if (rl   < cv){ m0=fmaxf(m0,acc[mf][nf][0]+b0); m1=fmaxf(m1,acc[mf][nf][1]+b1v); }
                if (rl+8 < cv){ m0=fmaxf(m0,acc[mf][nf][2]+b0); m1=fmaxf(m1,acc[mf][nf][3]+b1v); }
            }
#pragma unroll
            for (int off=4; off<32; off<<=1){
                m0=fmaxf(m0,__shfl_xor_sync(0xffffffffu,m0,off));
                m1=fmaxf(m1,__shfl_xor_sync(0xffffffffu,m1,off));
            }
            if (lane<4){ colmax[wid*128+c]=m0; colmax[wid*128+c+1]=m1; }
        }
        __syncthreads();
        {
            int cent=tid>>7, col=tid&127;
            int wb=(col>>6)*4 + cent*2;
            float m=fmaxf(colmax[wb*128+col], colmax[(wb+1)*128+col]);
            int cv = cent? cv1:cv0;
            float xv = cv? m : 0.f;
            x1[(size_t)(cg0+cent)*128+col] = xv;
            x1s[tid] = xv;
        }
        __syncthreads();
        {
            int cent=tid>>7, col=tid&127;
            const float* xr = x1s + cent*128;
            float s = w2as[16384+col];
            for (int k = 0; k < 128; ++k)
                s += xr[k]*w2as[k*128+col];
            y1[(size_t)(cg0+cent)*128+col] = s;
        }
    }
}

// ---- fused SA2 (R8) ----
__global__ void __launch_bounds__(256) sa2_fused_kernel(
    const float* __restrict__ y1, const float* __restrict__ pos1,
    const float* __restrict__ pos2, const int* __restrict__ nidx,
    const int* __restrict__ cnt, const float* __restrict__ W2a,
    const __nv_bfloat16* __restrict__ wbh, const __nv_bfloat16* __restrict__ wbl,
    const float* __restrict__ b2b,
    const __nv_bfloat16* __restrict__ wch, const __nv_bfloat16* __restrict__ wcl,
    const float* __restrict__ b2c,
    float* __restrict__ x2)
{
    constexpr int S = 136;
    extern __shared__ __align__(16) char sm2[];
    __nv_bfloat16* AsH = (__nv_bfloat16*)sm2;
    __nv_bfloat16* AsL = AsH + 128*S;
    __nv_bfloat16* WsH = AsL + 128*S;
    __nv_bfloat16* WsL = WsH + 128*S;
    float* w2a3  = (float*)(WsL + 128*S);
    float* colmax= w2a3 + 384;

    const int tid=threadIdx.x, lane=tid&31, wid=tid>>5;
    const int wm=wid&3, wn=wid>>2;
    const int cg0 = blockIdx.x*2;

    for (int t=tid; t<384; t+=256) w2a3[t]=W2a[16384+t];
    for (int t=tid; t<16384; t+=256){ int n=t>>7,k=t&127; WsH[n*S+k]=wbh[t]; WsL[n*S+k]=wbl[t]; }
    __syncthreads();

    {
        const int row=tid>>1, h0=(tid&1)*64;
        const int cg = cg0 + (row>>6);
        const int gp = (cg>>8)*M1C + nidx[cg*64 + (row&63)];
        const float rx = pos1[3*gp]  -pos2[3*cg];
        const float ry = pos1[3*gp+1]-pos2[3*cg+1];
        const float rz = pos1[3*gp+2]-pos2[3*cg+2];
        const float* yr = y1 + (size_t)gp*128;
#pragma unroll
        for (int j=0;j<64;++j){
            int n=h0+j;
            float v=fmaxf(yr[n]+rx*w2a3[n]+ry*w2a3[128+n]+rz*w2a3[256+n],0.f);
            splitf(v, AsH[row*S+n], AsL[row*S+n]);
        }
    }
    __syncthreads();

    float acc[2][8][4];
#pragma unroll
    for (int mf=0;mf<2;++mf)
#pragma unroll
        for (int nf=0;nf<8;++nf)
#pragma unroll
            for (int q=0;q<4;++q) acc[mf][nf][q]=0.f;
    mma_block<8,8,S>(acc, AsH, AsL, WsH, WsL, wm, wn*64, lane);
    __syncthreads();
#pragma unroll
    for (int mf=0;mf<2;++mf)
#pragma unroll
        for (int nf=0;nf<8;++nf){
            int r=wm*32+mf*16+(lane>>2);
            int c=wn*64+nf*8+(lane&3)*2;
            float b0=b2b[c], b1v=b2b[c+1];
            float v00=fmaxf(acc[mf][nf][0]+b0,0.f), v01=fmaxf(acc[mf][nf][1]+b1v,0.f);
            float v10=fmaxf(acc[mf][nf][2]+b0,0.f), v11=fmaxf(acc[mf][nf][3]+b1v,0.f);
            __nv_bfloat16 h0,l0,h1,l1;
            splitf(v00,h0,l0); splitf(v01,h1,l1);
            __nv_bfloat162 hh,ll;
            hh.x=h0; hh.y=h1; ll.x=l0; ll.y=l1;
            *(__nv_bfloat162*)&AsH[r*S+c]=hh; *(__nv_bfloat162*)&AsL[r*S+c]=ll;
            splitf(v10,h0,l0); splitf(v11,h1,l1);
            hh.x=h0; hh.y=h1; ll.x=l0; ll.y=l1;
            *(__nv_bfloat162*)&AsH[(r+8)*S+c]=hh; *(__nv_bfloat162*)&AsL[(r+8)*S+c]=ll;
        }

    const int cv0=cnt[cg0], cv1=cnt[cg0+1];
#pragma unroll
    for (int half=0; half<2; ++half){
        __syncthreads();
        for (int t=tid; t<16384; t+=256){
            int n=t>>7,k=t&127;
            WsH[n*S+k]=wch[half*16384+t]; WsL[n*S+k]=wcl[half*16384+t];
        }
        __syncthreads();
#pragma unroll
        for (int mf=0;mf<2;++mf)
#pragma unroll
            for (int nf=0;nf<8;++nf)
#pragma unroll
                for (int q=0;q<4;++q) acc[mf][nf][q]=0.f;
        mma_block<8,8,S>(acc, AsH, AsL, WsH, WsL, wm, wn*64, lane);
#pragma unroll
        for (int nf=0;nf<8;++nf){
            int c=wn*64+nf*8+(lane&3)*2;
            float b0=b2c[half*128+c], b1v=b2c[half*128+c+1];
            float m0=-FLT_MAX, m1=-FLT_MAX;
#pragma unroll
            for (int mf=0;mf<2;++mf){
                int r=wm*32+mf*16+(lane>>2);
                int cv=(r>>6)?cv1:cv0;
                int rl=r&63;
                if (rl   < cv){ m0=fmaxf(m0,acc[mf][nf][0]+b0); m1=fmaxf(m1,acc[mf][nf][1]+b1v); }
                if (rl+8 < cv){ m0=fmaxf(m0,acc[mf][nf][2]+b0); m1=fmaxf(m1,acc[mf][nf][3]+b1v); }
            }
#pragma unroll
            for (int off=4; off<32; off<<=1){
                m0=fmaxf(m0,__shfl_xor_sync(0xffffffffu,m0,off));
                m1=fmaxf(m1,__shfl_xor_sync(0xffffffffu,m1,off));
            }
            if (lane<4){ colmax[wid*128+c]=m0; colmax[wid*128+c+1]=m1; }
        }
        __syncthreads();
        {
            int cent=tid>>7, col=tid&127;
            int wb=(col>>6)*4 + cent*2;
            float m=fmaxf(colmax[wb*128+col], colmax[(wb+1)*128+col]);
            int cv = cent? cv1:cv0;
            x2[(size_t)(cg0+cent)*256 + half*128 + col] = cv? m : 0.f;
        }
    }
}

// ---- generic tensor-core GEMM: 128x64 tile, split bf16 ----
__global__ void __launch_bounds__(256) mma_gemm_kernel(
    const __nv_bfloat16* __restrict__ Ahi, const __nv_bfloat16* __restrict__ Alo,
    const __nv_bfloat16* __restrict__ Whi, const __nv_bfloat16* __restrict__ Wlo,
    const float* __restrict__ bias,
    float* __restrict__ outF,
    __nv_bfloat16* __restrict__ outHi, __nv_bfloat16* __restrict__ outLo,
    int N, int K, int relu)
{
    __shared__ __nv_bfloat16 AsH[128][34], AsL[128][34], WsH[64][34], WsL[64][34];
    const int tid = threadIdx.x;
    const int lane = tid & 31, wid = tid >> 5;
    const int wm = wid & 3, wn = wid >> 2;
    const int bm = blockIdx.y*128, bn = blockIdx.x*64;
    const int tcol = (tid & 15)*2, trow = tid >> 4;

    float acc[2][4][4];
#pragma unroll
    for (int mf=0; mf<2; ++mf)
#pragma unroll
        for (int nf=0; nf<4; ++nf)
#pragma unroll
            for (int q=0; q<4; ++q) acc[mf][nf][q]=0.f;

    for (int k0 = 0; k0 < K; k0 += 32) {
#pragma unroll
        for (int p = 0; p < 8; ++p) {
            int r = trow + p*16;
            size_t ga = (size_t)(bm + r)*K + k0 + tcol;
            *(unsigned*)&AsH[r][tcol] = *(const unsigned*)&Ahi[ga];
            *(unsigned*)&AsL[r][tcol] = *(const unsigned*)&Alo[ga];
        }
#pragma unroll
        for (int p = 0; p < 4; ++p) {
            int n = trow + p*16;
            size_t gw = (size_t)(bn + n)*K + k0 + tcol;
            *(unsigned*)&WsH[n][tcol] = *(const unsigned*)&Whi[gw];
            *(unsigned*)&WsL[n][tcol] = *(const unsigned*)&Wlo[gw];
        }
        __syncthreads();
#pragma unroll
        for (int ks = 0; ks < 2; ++ks) {
            const int kk = ks*16 + (lane&3)*2;
            unsigned ah[2][4], al[2][4], bh[4][2], bl[4][2];
#pragma unroll
            for (int mf=0; mf<2; ++mf) {
                int r = wm*32 + mf*16 + (lane>>2);
                ah[mf][0]=*(const unsigned*)&AsH[r][kk];
                ah[mf][1]=*(const unsigned*)&AsH[r+8][kk];
                ah[mf][2]=*(const unsigned*)&AsH[r][kk+8];
                ah[mf][3]=*(const unsigned*)&AsH[r+8][kk+8];
                al[mf][0]=*(const unsigned*)&AsL[r][kk];
                al[mf][1]=*(const unsigned*)&AsL[r+8][kk];
                al[mf][2]=*(const unsigned*)&AsL[r][kk+8];
                al[mf][3]=*(const unsigned*)&AsL[r+8][kk+8];
            }
#pragma unroll
            for (int nf=0; nf<4; ++nf) {
                int n = wn*32 + nf*8 + (lane>>2);
                bh[nf][0]=*(const unsigned*)&WsH[n][kk];
                bh[nf][1]=*(const unsigned*)&WsH[n][kk+8];
                bl[nf][0]=*(const unsigned*)&WsL[n][kk];
                bl[nf][1]=*(const unsigned*)&WsL[n][kk+8];
            }
#pragma unroll
            for (int mf=0; mf<2; ++mf)
#pragma unroll
                for (int nf=0; nf<4; ++nf) {
                    mma16816(acc[mf][nf], ah[mf], bh[nf]);
                    mma16816(acc[mf][nf], ah[mf], bl[nf]);
                    mma16816(acc[mf][nf], al[mf], bh[nf]);
                }
        }
        __syncthreads();
    }

#pragma unroll
    for (int mf=0; mf<2; ++mf)
#pragma unroll
        for (int nf=0; nf<4; ++nf) {
            int r = bm + wm*32 + mf*16 + (lane>>2);
            int c = bn + wn*32 + nf*8 + (lane&3)*2;
            float b0 = bias[c], b1 = bias[c+1];
            float v00 = acc[mf][nf][0]+b0, v01 = acc[mf][nf][1]+b1;
            float v10 = acc[mf][nf][2]+b0, v11 = acc[mf][nf][3]+b1;
            if (relu) {
                v00=fmaxf(v00,0.f); v01=fmaxf(v01,0.f);
                v10=fmaxf(v10,0.f); v11=fmaxf(v11,0.f);
            }
            if (outF) {
                outF[(size_t)r*N + c]   = v00; outF[(size_t)r*N + c+1]   = v01;
                outF[(size_t)(r+8)*N+c] = v10; outF[(size_t)(r+8)*N+c+1] = v11;
            }
            if (outHi) {
                __nv_bfloat16 h0,l0,h1,l1;
                splitf(v00,h0,l0); splitf(v01,h1,l1);
                __nv_bfloat162 hh; hh.x=h0; hh.y=h1;
                __nv_bfloat162 ll; ll.x=l0; ll.y=l1;
                *(__nv_bfloat162*)&outHi[(size_t)r*N + c] = hh;
                *(__nv_bfloat162*)&outLo[(size_t)r*N + c] = ll;
                splitf(v10,h0,l0); splitf(v11,h1,l1);
                hh.x=h0; hh.y=h1; ll.x=l0; ll.y=l1;
                *(__nv_bfloat162*)&outHi[(size_t)(r+8)*N + c] = hh;
                *(__nv_bfloat162*)&outLo[(size_t)(r+8)*N + c] = ll;
            }
        }
}

// ---- SA3 feature build ----
__global__ void feats3_split_kernel(const float* __restrict__ x2, const float* __restrict__ pos2,
                                    __nv_bfloat16* __restrict__ hi, __nv_bfloat16* __restrict__ lo)
{
    int row = blockIdx.x*2 + (threadIdx.x>>7);
    int c0 = threadIdx.x & 127;
    for (int c = c0; c < 288; c += 128) {
        float v = (c < 256) ? x2[(size_t)row*256 + c]
                : (c < 259) ? pos2[row*3 + c - 256] : 0.f;
        splitf(v, hi[(size_t)row*288 + c], lo[(size_t)row*288 + c]);
    }
}

__global__ void pool256_kernel(const float* __restrict__ g, float* __restrict__ gfeat)
{
    int b = blockIdx.y, f = blockIdx.x*256 + threadIdx.x;
    float m = -FLT_MAX;
    for (int r = 0; r < M2C; ++r)
        m = fmaxf(m, g[(size_t)(b*M2C+r)*1024 + f]);
    gfeat[b*1024+f]=m;
}

__global__ void head_kernel(const float* __restrict__ gfeat,
                            const float* __restrict__ Wh1, const float* __restrict__ bh1,
                            const float* __restrict__ Wh2, const float* __restrict__ bh2,
                            const float* __restrict__ Wh3, const float* __restrict__ bh3,
                            float* __restrict__ out)
{
    __shared__ float gf[1024], h1[512], h2[256], lg[10];
    const int b=blockIdx.x, tid=threadIdx.x;
    for (int i = tid; i < 1024; i += 256) gf[i]=gfeat[b*1024+i];
    __syncthreads();
    for (int n = tid; n < 512; n += 256) {
        float s = bh1[n];
        for (int k = 0; k < 1024; ++k) s += gf[k]*Wh1[(size_t)k*512+n];
        h1[n]=fmaxf(s,0.f);
    }
    __syncthreads();
    { float s = bh2[tid];
      for (int k = 0; k < 512; ++k) s += h1[k]*Wh2[(size_t)k*256+tid];
      h2[tid]=fmaxf(s,0.f); }
    __syncthreads();
    if (tid < 10) {
        float s = bh3[tid];
        for (int k = 0; k < 256; ++k) s += h2[k]*Wh3[k*10+tid];
        lg[tid]=s;
    }
    __syncthreads();
    if (tid == 0) {
        float m=lg[0];
        for (int j=1;j<10;++j) m=fmaxf(m,lg[j]);
        float se=0.f;
        for (int j=0;j<10;++j) se+=expf(lg[j]-m);
        float l=logf(se);
        for (int j=0;j<10;++j) out[b*10+j]=lg[j]-m-l;
    }
}

extern "C" void kernel_launch(void* const* d_in, const int* in_sizes, int n_in,
                              void* d_out, int out_size)
{
    const float* pos=(const float*)d_in[0];
    const float *W1a=(const float*)d_in[1],  *b1a=(const float*)d_in[2];
    const float *W1b=(const float*)d_in[3],  *b1b=(const float*)d_in[4];
    const float *W1c=(const float*)d_in[5],  *b1c=(const float*)d_in[6];
    const float *W2a=(const float*)d_in[7],  *b2a=(const float*)d_in[8];
    const float *W2b=(const float*)d_in[9],  *b2b=(const float*)d_in[10];
    const float *W2c=(const float*)d_in[11], *b2c=(const float*)d_in[12];
    const float *W3a=(const float*)d_in[13], *b3a=(const float*)d_in[14];
    const float *W3b=(const float*)d_in[15], *b3b=(const float*)d_in[16];
    const float *W3c=(const float*)d_in[17], *b3c=(const float*)d_in[18];
    const float *Wh1=(const float*)d_in[19], *bh1=(const float*)d_in[20];
    const float *Wh2=(const float*)d_in[21], *bh2=(const float*)d_in[22];
    const float *Wh3=(const float*)d_in[23], *bh3=(const float*)d_in[24];

    float *curv,*pos1,*curv1,*pos2,*x1,*x2,*gfeat,*fF,*bA;
    int *nidx1,*cnt1,*nidx2,*cnt2;
    __nv_bfloat16 *w1bh,*w1bl,*w1ch,*w1cl,*w2bh,*w2bl,*w2ch,*w2cl;
    __nv_bfloat16 *w3ah,*w3al,*w3bh,*w3bl,*w3ch,*w3cl;
    __nv_bfloat16 *pAh,*pAl,*pBh,*pBl,*pCh,*pCl;
    cudaGetSymbolAddress((void**)&curv, g_curv);
    cudaGetSymbolAddress((void**)&pos1, g_pos1);
    cudaGetSymbolAddress((void**)&curv1,g_curv1);
    cudaGetSymbolAddress((void**)&pos2, g_pos2);
    cudaGetSymbolAddress((void**)&nidx1,g_nidx1);
    cudaGetSymbolAddress((void**)&cnt1, g_cnt1);
    cudaGetSymbolAddress((void**)&nidx2,g_nidx2);
    cudaGetSymbolAddress((void**)&cnt2, g_cnt2);
    cudaGetSymbolAddress((void**)&x1,   g_x1);
    cudaGetSymbolAddress((void**)&x2,   g_x2);
    cudaGetSymbolAddress((void**)&gfeat,g_gfeat);
    cudaGetSymbolAddress((void**)&fF,   g_featF);
    cudaGetSymbolAddress((void**)&bA,   g_bufA);
    cudaGetSymbolAddress((void**)&w1bh, g_w1bh); cudaGetSymbolAddress((void**)&w1bl, g_w1bl);
    cudaGetSymbolAddress((void**)&w1ch, g_w1ch); cudaGetSymbolAddress((void**)&w1cl, g_w1cl);
    cudaGetSymbolAddress((void**)&w2bh, g_w2bh); cudaGetSymbolAddress((void**)&w2bl, g_w2bl);
    cudaGetSymbolAddress((void**)&w2ch, g_w2ch); cudaGetSymbolAddress((void**)&w2cl, g_w2cl);
    cudaGetSymbolAddress((void**)&w3ah, g_w3ah); cudaGetSymbolAddress((void**)&w3al, g_w3al);
    cudaGetSymbolAddress((void**)&w3bh, g_w3bh); cudaGetSymbolAddress((void**)&w3bl, g_w3bl);
    cudaGetSymbolAddress((void**)&w3ch, g_w3ch); cudaGetSymbolAddress((void**)&w3cl, g_w3cl);
    cudaGetSymbolAddress((void**)&pAh,  g_pAh);  cudaGetSymbolAddress((void**)&pAl,  g_pAl);
    cudaGetSymbolAddress((void**)&pBh,  g_pBh);  cudaGetSymbolAddress((void**)&pBl,  g_pBl);
    cudaGetSymbolAddress((void**)&pCh,  g_pCh);  cudaGetSymbolAddress((void**)&pCl,  g_pCl);

    cudaFuncSetAttribute(sa1_fused_kernel, cudaFuncAttributeMaxDynamicSharedMemorySize, 164352);
    cudaFuncSetAttribute(sa2_fused_kernel, cudaFuncAttributeMaxDynamicSharedMemorySize, 144896);

    cudaStream_t s2; cudaStreamCreateWithFlags(&s2, cudaStreamNonBlocking);
    cudaEvent_t e0, eW, e1, e2;
    cudaEventCreateWithFlags(&e0, cudaEventDisableTiming);
    cudaEventCreateWithFlags(&eW, cudaEventDisableTiming);
    cudaEventCreateWithFlags(&e1, cudaEventDisableTiming);
    cudaEventCreateWithFlags(&e2, cudaEventDisableTiming);

    // weight preps on s2 (R8 structure)
    cudaEventRecord(e0, 0);
    cudaStreamWaitEvent(s2, e0, 0);
    wprep_kernel<<<16, 256, 0, s2>>>(W1b, w1bh, w1bl, 64, 64);
    wprep_kernel<<<32, 256, 0, s2>>>(W1c, w1ch, w1cl, 64, 128);
    wprep_kernel<<<64, 256, 0, s2>>>(W2b, w2bh, w2bl, 128, 128);
    wprep_kernel<<<128,256, 0, s2>>>(W2c, w2ch, w2cl, 128, 256);
    wprep_pad_kernel<<<288, 256, 0, s2>>>(W3a, w3ah, w3al, 259, 256, 288);
    wprep_kernel<<<512, 256, 0, s2>>>(W3b, w3bh, w3bl, 256, 512);
    wprep_kernel<<<2048,256, 0, s2>>>(W3c, w3ch, w3cl, 512, 1024);
    cudaEventRecord(eW, s2);

    // curvature (split-scan, 256 thr) + FPS1 (fused gather -> pos1/curv1)
    curvature_kernel<<<BATCH*(NPT/128), 256>>>(pos, curv);
    fps_kernel<NPT,M1C><<<BATCH, 256>>>(pos, curv, pos1, curv1);
    cudaEventRecord(e1, 0);

    // branch B on s2: FPS2 + group2
    cudaStreamWaitEvent(s2, e1, 0);
    fps_kernel<M1C,M2C><<<BATCH, 256, 0, s2>>>(pos1, curv1, pos2, (float*)0);
    group_kernel<M1C,512,4><<<dim3(M2C/4, BATCH), 128, 0, s2>>>(pos1, pos2, nidx2, cnt2, M2C, 0.16f);
    cudaEventRecord(e2, s2);

    // branch A on main: group1 + SA1 (writes x1 AND y1)
    group_kernel<NPT,128,8><<<dim3(M1C/8, BATCH), 256>>>(pos, pos1, nidx1, cnt1, M1C, 0.04f);
    cudaStreamWaitEvent(0, eW, 0);
    sa1_fused_kernel<<<152, 256, 164352>>>(pos, pos1, nidx1, cnt1,
        W1a, b1a, w1bh, w1bl, b1b, w1ch, w1cl, b1c, W2a, b2a, x1, fF);

    // join, SA2
    cudaStreamWaitEvent(0, e2, 0);
    sa2_fused_kernel<<<BATCH*M2C/2, 256, 144896>>>(fF, pos1, pos2, nidx2, cnt2,
        W2a, w2bh, w2bl, b2b, w2ch, w2cl, b2c, x2);

    // SA3 on tensor cores
    feats3_split_kernel<<<BATCH*M2C/2, 256>>>(x2, pos2, pAh, pAl);
    mma_gemm_kernel<<<dim3(4, 16), 256>>>(pAh, pAl, w3ah, w3al, b3a,
                                          (float*)0, pBh, pBl, 256, 288, 1);
    mma_gemm_kernel<<<dim3(8, 16), 256>>>(pBh, pBl, w3bh, w3bl, b3b,
                                          (float*)0, pCh, pCl, 512, 256, 1);
    mma_gemm_kernel<<<dim3(16, 16), 256>>>(pCh, pCl, w3ch, w3cl, b3c,
                                           bA, (__nv_bfloat16*)0, (__nv_bfloat16*)0, 1024, 512, 0);
    pool256_kernel<<<dim3(4, BATCH), 256>>>(bA, gfeat);

    // head
    head_kernel<<<BATCH, 256>>>(gfeat, Wh1, bh1, Wh2, bh2, Wh3, bh3, (float*)d_out);
}

// round 16
// speedup vs baseline: 1.2802x; 1.0021x over previous
#include <cuda_runtime.h>
#include <cuda_bf16.h>
#include <math.h>
#include <float.h>

#define BATCH 8
#define NPT   2048
#define M1C   1024
#define M2C   256
#define KNB   64
#define CURVK 10

// ---- scratch (device globals; no allocation) ----
__device__ float g_curv [BATCH*NPT];
__device__ float g_pos1 [BATCH*M1C*3];
__device__ float g_curv1[BATCH*M1C];
__device__ float g_pos2 [BATCH*M2C*3];
__device__ int   g_nidx1[BATCH*M1C*KNB];
__device__ int   g_cnt1 [BATCH*M1C];
__device__ int   g_nidx2[BATCH*M2C*KNB];
__device__ int   g_cnt2 [BATCH*M2C];
__device__ float g_x1   [BATCH*M1C*128];
__device__ float g_x2   [BATCH*M2C*256];
__device__ float g_gfeat[BATCH*1024];
__device__ float g_featF[1024*1024];          // y1 (8192x128)
__device__ float g_bufA [2*1024*1024];        // SA3 final fp32 (2048x1024)
__device__ __nv_bfloat16 g_w1bh[4096],  g_w1bl[4096];
__device__ __nv_bfloat16 g_w1ch[8192],  g_w1cl[8192];
__device__ __nv_bfloat16 g_w2bh[16384], g_w2bl[16384];
__device__ __nv_bfloat16 g_w2ch[32768], g_w2cl[32768];
__device__ __nv_bfloat16 g_w3ah[73728], g_w3al[73728];
__device__ __nv_bfloat16 g_w3bh[131072],g_w3bl[131072];
__device__ __nv_bfloat16 g_w3ch[524288],g_w3cl[524288];
__device__ __nv_bfloat16 g_pAh[589824], g_pAl[589824];
__device__ __nv_bfloat16 g_pBh[524288], g_pBl[524288];
__device__ __nv_bfloat16 g_pCh[1048576],g_pCl[1048576];

__device__ __forceinline__ void splitf(float v, __nv_bfloat16& h, __nv_bfloat16& l) {
    h = __float2bfloat16(v);
    l = __float2bfloat16(v - __bfloat162float(h));
}

__device__ __forceinline__ void mma16816(float* c, const unsigned* a, const unsigned* b) {
    asm volatile(
      "mma.sync.aligned.m16n8k16.row.col.f32.bf16.bf16.f32 "
      "{%0,%1,%2,%3}, {%4,%5,%6,%7}, {%8,%9}, {%0,%1,%2,%3};\n"
      : "+f"(c[0]), "+f"(c[1]), "+f"(c[2]), "+f"(c[3])
      : "r"(a[0]), "r"(a[1]), "r"(a[2]), "r"(a[3]), "r"(b[0]), "r"(b[1]));
}

template<int NF,int K16,int S>
__device__ __forceinline__ void mma_block(
    float (&acc)[2][8][4],
    const __nv_bfloat16* AsH, const __nv_bfloat16* AsL,
    const __nv_bfloat16* WH,  const __nv_bfloat16* WL,
    int wm, int wnbase, int lane)
{
#pragma unroll
    for (int k16=0;k16<K16;++k16){
        const int kk=k16*16+(lane&3)*2;
        unsigned ah[2][4], al[2][4];
#pragma unroll
        for (int mf=0;mf<2;++mf){
            int r=wm*32+mf*16+(lane>>2);
            ah[mf][0]=*(const unsigned*)&AsH[r*S+kk];
            ah[mf][1]=*(const unsigned*)&AsH[(r+8)*S+kk];
            ah[mf][2]=*(const unsigned*)&AsH[r*S+kk+8];
            ah[mf][3]=*(const unsigned*)&AsH[(r+8)*S+kk+8];
            al[mf][0]=*(const unsigned*)&AsL[r*S+kk];
            al[mf][1]=*(const unsigned*)&AsL[(r+8)*S+kk];
            al[mf][2]=*(const unsigned*)&AsL[r*S+kk+8];
            al[mf][3]=*(const unsigned*)&AsL[(r+8)*S+kk+8];
        }
#pragma unroll
        for (int nf=0;nf<NF;++nf){
            int n=wnbase+nf*8+(lane>>2);
            unsigned bh[2]={*(const unsigned*)&WH[n*S+kk], *(const unsigned*)&WH[n*S+kk+8]};
            unsigned bl[2]={*(const unsigned*)&WL[n*S+kk], *(const unsigned*)&WL[n*S+kk+8]};
#pragma unroll
            for (int mf=0;mf<2;++mf){
                mma16816(acc[mf][nf], ah[mf], bh);
                mma16816(acc[mf][nf], ah[mf], bl);
                mma16816(acc[mf][nf], al[mf], bh);
            }
        }
    }
}

// ---- curvature: 2 threads per query, half-scans merged (bitwise-identical sets) ----
__global__ void __launch_bounds__(256) curvature_kernel(const float* __restrict__ pos,
                                                        float* __restrict__ curv)
{
    __shared__ float px[NPT], py[NPT], pz[NPT], nr[NPT];
    __shared__ float sd[256*CURVK];
    __shared__ int   si[256*CURVK];
    const int b = blockIdx.x / (NPT/128);
    const int tid = threadIdx.x;
    const float* cp = pos + (size_t)b * NPT * 3;
    for (int i = tid; i < NPT; i += 256) {
        float x = cp[3*i], y = cp[3*i+1], z = cp[3*i+2];
        px[i]=x; py[i]=y; pz[i]=z; nr[i]=x*x+y*y+z*z;
    }
    __syncthreads();
    const int q = (blockIdx.x % (NPT/128)) * 128 + (tid & 127);
    const int half = tid >> 7;
    const int jlo = half*1024, jhi = jlo+1024;
    const float qx=px[q], qy=py[q], qz=pz[q], nq=nr[q];

    float td[CURVK]; int ti[CURVK];
#pragma unroll
    for (int s = 0; s < CURVK; ++s) { td[s]=3.4e38f; ti[s]=0; }
#pragma unroll 8
    for (int j = jlo; j < jhi; ++j) {
        float d2 = nq + nr[j] - 2.0f*(qx*px[j]+qy*py[j]+qz*pz[j]);
        if (d2 < td[CURVK-1]) {
            float cd=d2; int ci=j;
#pragma unroll
            for (int s = 0; s < CURVK; ++s)
                if (cd < td[s]) { float t=td[s]; td[s]=cd; cd=t; int u=ti[s]; ti[s]=ci; ci=u; }
        }
    }
#pragma unroll
    for (int s = 0; s < CURVK; ++s) { sd[tid*CURVK+s]=td[s]; si[tid*CURVK+s]=ti[s]; }
    __syncthreads();
    if (half) return;

    // merge own (left, lower indices) with partner (right) — ties prefer left
    float md_[CURVK]; int mi_[CURVK];
    {
        const float* ld = &sd[tid*CURVK];        const int* li = &si[tid*CURVK];
        const float* rd = &sd[(tid+128)*CURVK];  const int* ri = &si[(tid+128)*CURVK];
        int a=0, c=0;
#pragma unroll
        for (int s = 0; s < CURVK; ++s) {
            float dl = ld[a], dr = rd[c];
            if (dl <= dr) { md_[s]=dl; mi_[s]=li[a]; ++a; }
            else          { md_[s]=dr; mi_[s]=ri[c]; ++c; }
        }
    }

    float mx=0,my=0,mz=0;
#pragma unroll
    for (int s = 0; s < CURVK; ++s) { mx+=px[mi_[s]]; my+=py[mi_[s]]; mz+=pz[mi_[s]]; }
    mx/=CURVK; my/=CURVK; mz/=CURVK;
    double cxx=0,cxy=0,cxz=0,cyy=0,cyz=0,czz=0;
#pragma unroll
    for (int s = 0; s < CURVK; ++s) {
        float ax=px[mi_[s]]-mx, ay=py[mi_[s]]-my, az=pz[mi_[s]]-mz;
        cxx+=(double)ax*ax; cxy+=(double)ax*ay; cxz+=(double)ax*az;
        cyy+=(double)ay*ay; cyz+=(double)ay*az; czz+=(double)az*az;
    }
    cxx/=CURVK; cxy/=CURVK; cxz/=CURVK; cyy/=CURVK; cyz/=CURVK; czz/=CURVK;
    double tr=cxx+cyy+czz;
    double p1=cxy*cxy+cxz*cxz+cyz*cyz;
    double qv=tr/3.0;
    double p2=(cxx-qv)*(cxx-qv)+(cyy-qv)*(cyy-qv)+(czz-qv)*(czz-qv)+2.0*p1;
    double lmin;
    if (p2 < 1e-32) lmin = qv;
    else {
        double p=sqrt(p2/6.0);
        double b00=(cxx-qv)/p,b11=(cyy-qv)/p,b22=(czz-qv)/p,b01=cxy/p,b02=cxz/p,b12=cyz/p;
        double detB=b00*(b11*b22-b12*b12)-b01*(b01*b22-b12*b02)+b02*(b01*b12-b11*b02);
        double r=fmin(1.0,fmax(-1.0,detB*0.5));
        lmin=qv+2.0*p*cos(acos(r)/3.0 + 2.0943951023931953);
    }
    curv[b*NPT+q]=(float)(lmin/(tr+1e-8));
}

// ---- weighted FPS with fused gather (R8 body, 256 thr) ----
template<int NPTS,int MOUT>
__global__ void __launch_bounds__(256) fps_kernel(const float* __restrict__ pos,
                                                  const float* __restrict__ curv,
                                                  float* __restrict__ opos,
                                                  float* __restrict__ ocurv)
{
    constexpr int THR=256, E=NPTS/THR, NW=8;
    __shared__ float spx[NPTS], spy[NPTS], spz[NPTS], scv[NPTS];
    __shared__ unsigned long long wkey[2][NW];
    const int b=blockIdx.x, tid=threadIdx.x, lane=tid&31, wid=tid>>5;
    const float* cp = pos + (size_t)b*NPTS*3;
    float px[E],py[E],pz[E],ww[E],md[E];
#pragma unroll
    for (int e=0;e<E;++e){
        int i=tid+e*THR;
        float x=cp[3*i], y=cp[3*i+1], z=cp[3*i+2];
        float cv=curv[b*NPTS+i];
        px[e]=x; py[e]=y; pz[e]=z;
        spx[i]=x; spy[i]=y; spz[i]=z; scv[i]=cv;
        ww[e]=1.0f+10.0f*cv;
        md[e]=FLT_MAX;
    }
    __syncthreads();
    float sx=spx[0], sy=spy[0], sz=spz[0];
    if (tid==0){
        int o=b*MOUT;
        opos[3*o]=sx; opos[3*o+1]=sy; opos[3*o+2]=sz;
        if (ocurv) ocurv[o]=scv[0];
    }
    for (int m=1;m<MOUT;++m){
        float bv=-1.f; int bi=0;
#pragma unroll
        for (int e=0;e<E;++e){
            int i=tid+e*THR;
            float dx=px[e]-sx, dy=py[e]-sy, dz=pz[e]-sz;
            float d=fminf(md[e], dx*dx+dy*dy+dz*dz);
            md[e]=d;
            float v=d*ww[e];
            if (v>bv){ bv=v; bi=i; }   // i increasing per thread -> first max kept
        }
        unsigned hv=__float_as_uint(bv);
        unsigned hm=__reduce_max_sync(0xffffffffu, hv);
        unsigned lm=__reduce_max_sync(0xffffffffu, (hv==hm)? ~(unsigned)bi : 0u);
        if (lane==0) wkey[m&1][wid]=((unsigned long long)hm<<32)|lm;
        __syncthreads();
        unsigned long long k2 = (lane<NW)? wkey[m&1][lane] : 0ull;
        unsigned h2=(unsigned)(k2>>32), l2=(unsigned)k2;
        unsigned hm2=__reduce_max_sync(0xffffffffu, h2);
        unsigned lm2=__reduce_max_sync(0xffffffffu, (h2==hm2)? l2 : 0u);
        int s=(int)(~lm2);
        sx=spx[s]; sy=spy[s]; sz=spz[s];
        if (tid==0){
            int o=b*MOUT+m;
            opos[3*o]=sx; opos[3*o+1]=sy; opos[3*o+2]=sz;
            if (ocurv) ocurv[o]=scv[s];
        }
    }
}

// ---- radius grouping (R8 config) ----
template<int NPTS,int CAP,int CPB>
__global__ void group_kernel(const float* __restrict__ pts, const float* __restrict__ cents,
                             int* __restrict__ nidx, int* __restrict__ cnt_out,
                             int MC, float r2)
{
    __shared__ float px[NPTS],py[NPTS],pz[NPTS],nr[NPTS];
    __shared__ unsigned long long cand[CPB][CAP];
    const int b=blockIdx.y, tid=threadIdx.x;
    const float* cp = pts + (size_t)b*NPTS*3;
    for (int i = tid; i < NPTS; i += CPB*32) {
        float x=cp[3*i],y=cp[3*i+1],z=cp[3*i+2];
        px[i]=x; py[i]=y; pz[i]=z; nr[i]=x*x+y*y+z*z;
    }
    __syncthreads();
    const int w=tid>>5, lane=tid&31;
    const int c=blockIdx.x*CPB+w, cg=b*MC+c;
    const float cx=cents[3*cg],cy=cents[3*cg+1],cz=cents[3*cg+2];
    const float nc=cx*cx+cy*cy+cz*cz;
    int cnt=0;
    for (int j0 = 0; j0 < NPTS; j0 += 32) {
        int j=j0+lane;
        float d2 = nc + nr[j] - 2.0f*(cx*px[j]+cy*py[j]+cz*pz[j]);
        bool in = (d2 <= r2);
        unsigned mask = __ballot_sync(0xffffffffu, in);
        if (in) {
            int p = cnt + __popc(mask & ((1u<<lane)-1u));
            if (p < CAP) {
                unsigned ub=__float_as_uint(d2);
                ub = (ub&0x80000000u) ? ~ub : (ub|0x80000000u);
                cand[w][p] = ((unsigned long long)ub<<32) | (unsigned)j;
            }
        }
        cnt += __popc(mask);
    }
    if (cnt > CAP) cnt = CAP;
    for (int i = cnt+lane; i < CAP; i += 32) cand[w][i]=0xFFFFFFFFFFFFFFFFull;
    __syncwarp();
    for (int k = 2; k <= CAP; k <<= 1)
        for (int j = k>>1; j > 0; j >>= 1) {
            for (int i = lane; i < CAP; i += 32) {
                int ixj = i^j;
                if (ixj > i) {
                    unsigned long long a=cand[w][i], bb=cand[w][ixj];
                    if ((a>bb) == ((i&k)==0)) { cand[w][i]=bb; cand[w][ixj]=a; }
                }
            }
            __syncwarp();
        }
    int nv = cnt < KNB ? cnt : KNB;
    int fb = (nv>0) ? (int)(cand[w][0]&0xffffffffu) : 0;
    for (int i = lane; i < KNB; i += 32)
        nidx[(size_t)cg*KNB+i] = (i<nv) ? (int)(cand[w][i]&0xffffffffu) : fb;
    if (lane==0) cnt_out[cg]=nv;
}

// ---- weight prep (R8: separate kernels) ----
__global__ void wprep_kernel(const float* __restrict__ W,
                             __nv_bfloat16* __restrict__ hi, __nv_bfloat16* __restrict__ lo,
                             int K, int N)
{
    int t = blockIdx.x*256 + threadIdx.x;
    if (t >= K*N) return;
    int n = t / K, k = t % K;
    __nv_bfloat16 h,l; splitf(W[(size_t)k*N + n], h, l);
    hi[t]=h; lo[t]=l;
}
__global__ void wprep_pad_kernel(const float* __restrict__ W,
                                 __nv_bfloat16* __restrict__ hi, __nv_bfloat16* __restrict__ lo,
                                 int K, int N, int Kpad)
{
    int t = blockIdx.x*256 + threadIdx.x;
    if (t >= N*Kpad) return;
    int n = t / Kpad, k = t % Kpad;
    float v = (k < K) ? W[(size_t)k*N + n] : 0.f;
    __nv_bfloat16 h,l; splitf(v, h, l);
    hi[t]=h; lo[t]=l;
}

// ---- fused SA1 (persistent, grid 304, 2 blocks/SM) + y1 epilogue via __ldg ----
__global__ void __launch_bounds__(256) sa1_fused_kernel(
    const float* __restrict__ pos, const float* __restrict__ pos1,
    const int* __restrict__ nidx, const int* __restrict__ cnt,
    const float* __restrict__ W1a, const float* __restrict__ b1a,
    const __nv_bfloat16* __restrict__ wbh, const __nv_bfloat16* __restrict__ wbl,
    const float* __restrict__ b1b,
    const __nv_bfloat16* __restrict__ wch, const __nv_bfloat16* __restrict__ wcl,
    const float* __restrict__ b1c,
    const float* __restrict__ W2a, const float* __restrict__ b2a,
    float* __restrict__ x1, float* __restrict__ y1)
{
    constexpr int S = 72;
    extern __shared__ __align__(16) char sm1[];
    __nv_bfloat16* AsH = (__nv_bfloat16*)sm1;
    __nv_bfloat16* AsL = AsH + 128*S;
    __nv_bfloat16* WcH = AsL + 128*S;
    __nv_bfloat16* WcL = WcH + 128*S;
    __nv_bfloat16* WbH = WcL + 128*S;
    __nv_bfloat16* WbL = WbH + 64*S;
    float* w1s   = (float*)(WbL + 64*S);   // 192 W1a + 64 b1a
    float* colmax= w1s + 256;              // [8][128]
    float* x1s   = colmax + 1024;          // 256
    // total: 92160 + (256+1024+256)*4 = 98304 bytes -> 2 blocks/SM

    const int tid=threadIdx.x, lane=tid&31, wid=tid>>5;
    const int wm=wid&3, wn=wid>>2;

    for (int t=tid; t<64*64;  t+=256){ int n=t>>6,k=t&63; WbH[n*S+k]=wbh[t]; WbL[n*S+k]=wbl[t]; }
    for (int t=tid; t<128*64; t+=256){ int n=t>>6,k=t&63; WcH[n*S+k]=wch[t]; WcL[n*S+k]=wcl[t]; }
    if (tid<192) w1s[tid]=W1a[tid];
    else if (tid<256) w1s[tid]=b1a[tid-192];

    const int NT = BATCH*M1C/2;
    for (int tile = blockIdx.x; tile < NT; tile += gridDim.x) {
        const int cg0 = tile*2;
        __syncthreads();
        {
            const int row=tid>>1, h0=(tid&1)*32;
            const int cg = cg0 + (row>>6);
            const int p  = nidx[cg*64 + (row&63)];
            const int src = (cg>>10)*NPT + p;
            const float rx = pos[3*src]  -pos1[3*cg];
            const float ry = pos[3*src+1]-pos1[3*cg+1];
            const float rz = pos[3*src+2]-pos1[3*cg+2];
#pragma unroll
            for (int j=0;j<32;++j){
                int n=h0+j;
                float v=fmaxf(rx*w1s[n]+ry*w1s[64+n]+rz*w1s[128+n]+w1s[192+n],0.f);
                splitf(v, AsH[row*S+n], AsL[row*S+n]);
            }
        }
        __syncthreads();

        float acc[2][8][4];
#pragma unroll
        for (int mf=0;mf<2;++mf)
#pragma unroll
            for (int nf=0;nf<4;++nf)
#pragma unroll
                for (int q=0;q<4;++q) acc[mf][nf][q]=0.f;
        mma_block<4,4,S>(acc, AsH, AsL, WbH, WbL, wm, wn*32, lane);
        __syncthreads();
#pragma unroll
        for (int mf=0;mf<2;++mf)
#pragma unroll
            for (int nf=0;nf<4;++nf){
                int r=wm*32+mf*16+(lane>>2);
                int c=wn*32+nf*8+(lane&3)*2;
                float b0=b1b[c], b1v=b1b[c+1];
                float v00=fmaxf(acc[mf][nf][0]+b0,0.f), v01=fmaxf(acc[mf][nf][1]+b1v,0.f);
                float v10=fmaxf(acc[mf][nf][2]+b0,0.f), v11=fmaxf(acc[mf][nf][3]+b1v,0.f);
                __nv_bfloat16 h0,l0,h1,l1;
                splitf(v00,h0,l0); splitf(v01,h1,l1);
                __nv_bfloat162 hh,ll;
                hh.x=h0; hh.y=h1; ll.x=l0; ll.y=l1;
                *(__nv_bfloat162*)&AsH[r*S+c]=hh; *(__nv_bfloat162*)&AsL[r*S+c]=ll;
                splitf(v10,h0,l0); splitf(v11,h1,l1);
                hh.x=h0; hh.y=h1; ll.x=l0; ll.y=l1;
                *(__nv_bfloat162*)&AsH[(r+8)*S+c]=hh; *(__nv_bfloat162*)&AsL[(r+8)*S+c]=ll;
            }
        __syncthreads();

#pragma unroll
        for (int mf=0;mf<2;++mf)
#pragma unroll
            for (int nf=0;nf<8;++nf)
#pragma unroll
                for (int q=0;q<4;++q) acc[mf][nf][q]=0.f;
        mma_block<8,4,S>(acc, AsH, AsL, WcH, WcL, wm, wn*64, lane);

        const int cv0=cnt[cg0], cv1=cnt[cg0+1];
#pragma unroll
        for (int nf=0;nf<8;++nf){
            int c=wn*64+nf*8+(lane&3)*2;
            float b0=b1c[c], b1v=b1c[c+1];
            float m0=-FLT_MAX, m1=-FLT_MAX;
#pragma unroll
            for (int mf=0;mf<2;++mf){
                int r=wm*32+mf*16+(lane>>2);
                int cv=(r>>6)?cv1:cv0;
                int rl=r&63;
                if (rl   < cv){ m0=fmaxf(m0,acc[mf][nf][0]+b0); m1=fmaxf(m1,acc[mf][nf][1]+b1v); }
                if (rl+8 < cv){ m0=fmaxf(m0,acc[mf][nf][2]+b0); m1=fmaxf(m1,acc[mf][nf][3]+b1v); }
            }
#pragma unroll
            for (int off=4; off<32; off<<=1){
                m0=fmaxf(m0,__shfl_xor_sync(0xffffffffu,m0,off));
                m1=fmaxf(m1,__shfl_xor_sync(0xffffffffu,m1,off));
            }
            if (lane<4){ colmax[wid*128+c]=m0; colmax[wid*128+c+1]=m1; }
        }
        __syncthreads();
        {
            int cent=tid>>7, col=tid&127;
            int wb=(col>>6)*4 + cent*2;
            float m=fmaxf(colmax[wb*128+col], colmax[(wb+1)*128+col]);
            int cv = cent? cv1:cv0;
            float xv = cv? m : 0.f;
            x1[(size_t)(cg0+cent)*128+col] = xv;
            x1s[tid] = xv;
        }
        __syncthreads();
        // y1 epilogue: y1[row] = x1[row] @ W2a + b2a (fp32, LDG weights, identical order)
        {
            int cent=tid>>7, col=tid&127;
            const float* xr = x1s + cent*128;
            float s = __ldg(&b2a[col]);
#pragma unroll 8
            for (int k = 0; k < 128; ++k)
                s += xr[k]*__ldg(&W2a[k*128+col]);
            y1[(size_t)(cg0+cent)*128+col] = s;
        }
    }
}

// ---- fused SA2 (R8) ----
__global__ void __launch_bounds__(256) sa2_fused_kernel(
    const float* __restrict__ y1, const float* __restrict__ pos1,
    const float* __restrict__ pos2, const int* __restrict__ nidx,
    const int* __restrict__ cnt, const float* __restrict__ W2a,
    const __nv_bfloat16* __restrict__ wbh, const __nv_bfloat16* __restrict__ wbl,
    const float* __restrict__ b2b,
    const __nv_bfloat16* __restrict__ wch, const __nv_bfloat16* __restrict__ wcl,
    const float* __restrict__ b2c,
    float* __restrict__ x2)
{
    constexpr int S = 136;
    extern __shared__ __align__(16) char sm2[];
    __nv_bfloat16* AsH = (__nv_bfloat16*)sm2;
    __nv_bfloat16* AsL = AsH + 128*S;
    __nv_bfloat16* WsH = AsL + 128*S;
    __nv_bfloat16* WsL = WsH + 128*S;
    float* w2a3  = (float*)(WsL + 128*S);
    float* colmax= w2a3 + 384;

    const int tid=threadIdx.x, lane=tid&31, wid=tid>>5;
    const int wm=wid&3, wn=wid>>2;
    const int cg0 = blockIdx.x*2;

    for (int t=tid; t<384; t+=256) w2a3[t]=W2a[16384+t];
    for (int t=tid; t<16384; t+=256){ int n=t>>7,k=t&127; WsH[n*S+k]=wbh[t]; WsL[n*S+k]=wbl[t]; }
    __syncthreads();

    {
        const int row=tid>>1, h0=(tid&1)*64;
        const int cg = cg0 + (row>>6);
        const int gp = (cg>>8)*M1C + nidx[cg*64 + (row&63)];
        const float rx = pos1[3*gp]  -pos2[3*cg];
        const float ry = pos1[3*gp+1]-pos2[3*cg+1];
        const float rz = pos1[3*gp+2]-pos2[3*cg+2];
        const float* yr = y1 + (size_t)gp*128;
#pragma unroll
        for (int j=0;j<64;++j){
            int n=h0+j;
            float v=fmaxf(yr[n]+rx*w2a3[n]+ry*w2a3[128+n]+rz*w2a3[256+n],0.f);
            splitf(v, AsH[row*S+n], AsL[row*S+n]);
        }
    }
    __syncthreads();

    float acc[2][8][4];
#pragma unroll
    for (int mf=0;mf<2;++mf)
#pragma unroll
        for (int nf=0;nf<8;++nf)
#pragma unroll
            for (int q=0;q<4;++q) acc[mf][nf][q]=0.f;
    mma_block<8,8,S>(acc, AsH, AsL, WsH, WsL, wm, wn*64, lane);
    __syncthreads();
#pragma unroll
    for (int mf=0;mf<2;++mf)
#pragma unroll
        for (int nf=0;nf<8;++nf){
            int r=wm*32+mf*16+(lane>>2);
            int c=wn*64+nf*8+(lane&3)*2;
            float b0=b2b[c], b1v=b2b[c+1];
            float v00=fmaxf(acc[mf][nf][0]+b0,0.f), v01=fmaxf(acc[mf][nf][1]+b1v,0.f);
            float v10=fmaxf(acc[mf][nf][2]+b0,0.f), v11=fmaxf(acc[mf][nf][3]+b1v,0.f);
            __nv_bfloat16 h0,l0,h1,l1;
            splitf(v00,h0,l0); splitf(v01,h1,l1);
            __nv_bfloat162 hh,ll;
            hh.x=h0; hh.y=h1; ll.x=l0; ll.y=l1;
            *(__nv_bfloat162*)&AsH[r*S+c]=hh; *(__nv_bfloat162*)&AsL[r*S+c]=ll;
            splitf(v10,h0,l0); splitf(v11,h1,l1);
            hh.x=h0; hh.y=h1; ll.x=l0; ll.y=l1;
            *(__nv_bfloat162*)&AsH[(r+8)*S+c]=hh; *(__nv_bfloat162*)&AsL[(r+8)*S+c]=ll;
        }

    const int cv0=cnt[cg0], cv1=cnt[cg0+1];
#pragma unroll
    for (int half=0; half<2; ++half){
        __syncthreads();
        for (int t=tid; t<16384; t+=256){
            int n=t>>7,k=t&127;
            WsH[n*S+k]=wch[half*16384+t]; WsL[n*S+k]=wcl[half*16384+t];
        }
        __syncthreads();
#pragma unroll
        for (int mf=0;mf<2;++mf)
#pragma unroll
            for (int nf=0;nf<8;++nf)
#pragma unroll
                for (int q=0;q<4;++q) acc[mf][nf][q]=0.f;
        mma_block<8,8,S>(acc, AsH, AsL, WsH, WsL, wm, wn*64, lane);
#pragma unroll
        for (int nf=0;nf<8;++nf){
            int c=wn*64+nf*8+(lane&3)*2;
            float b0=b2c[half*128+c], b1v=b2c[half*128+c+1];
            float m0=-FLT_MAX, m1=-FLT_MAX;
#pragma unroll
            for (int mf=0;mf<2;++mf){
                int r=wm*32+mf*16+(lane>>2);
                int cv=(r>>6)?cv1:cv0;
                int rl=r&63;
                if (rl   < cv){ m0=fmaxf(m0,acc[mf][nf][0]+b0); m1=fmaxf(m1,acc[mf][nf][1]+b1v); }
                if (rl+8 < cv){ m0=fmaxf(m0,acc[mf][nf][2]+b0); m1=fmaxf(m1,acc[mf][nf][3]+b1v); }
            }
#pragma unroll
            for (int off=4; off<32; off<<=1){
                m0=fmaxf(m0,__shfl_xor_sync(0xffffffffu,m0,off));
                m1=fmaxf(m1,__shfl_xor_sync(0xffffffffu,m1,off));
            }
            if (lane<4){ colmax[wid*128+c]=m0; colmax[wid*128+c+1]=m1; }
        }
        __syncthreads();
        {
            int cent=tid>>7, col=tid&127;
            int wb=(col>>6)*4 + cent*2;
            float m=fmaxf(colmax[wb*128+col], colmax[(wb+1)*128+col]);
            int cv = cent? cv1:cv0;
            x2[(size_t)(cg0+cent)*256 + half*128 + col] = cv? m : 0.f;
        }
    }
}

// ---- generic tensor-core GEMM: 128x64 tile, split bf16 ----
__global__ void __launch_bounds__(256) mma_gemm_kernel(
    const __nv_bfloat16* __restrict__ Ahi, const __nv_bfloat16* __restrict__ Alo,
    const __nv_bfloat16* __restrict__ Whi, const __nv_bfloat16* __restrict__ Wlo,
    const float* __restrict__ bias,
    float* __restrict__ outF,
    __nv_bfloat16* __restrict__ outHi, __nv_bfloat16* __restrict__ outLo,
    int N, int K, int relu)
{
    __shared__ __nv_bfloat16 AsH[128][34], AsL[128][34], WsH[64][34], WsL[64][34];
    const int tid = threadIdx.x;
    const int lane = tid & 31, wid = tid >> 5;
    const int wm = wid & 3, wn = wid >> 2;
    const int bm = blockIdx.y*128, bn = blockIdx.x*64;
    const int tcol = (tid & 15)*2, trow = tid >> 4;

    float acc[2][4][4];
#pragma unroll
    for (int mf=0; mf<2; ++mf)
#pragma unroll
        for (int nf=0; nf<4; ++nf)
#pragma unroll
            for (int q=0; q<4; ++q) acc[mf][nf][q]=0.f;

    for (int k0 = 0; k0 < K; k0 += 32) {
#pragma unroll
        for (int p = 0; p < 8; ++p) {
            int r = trow + p*16;
            size_t ga = (size_t)(bm + r)*K + k0 + tcol;
            *(unsigned*)&AsH[r][tcol] = *(const unsigned*)&Ahi[ga];
            *(unsigned*)&AsL[r][tcol] = *(const unsigned*)&Alo[ga];
        }
#pragma unroll
        for (int p = 0; p < 4; ++p) {
            int n = trow + p*16;
            size_t gw = (size_t)(bn + n)*K + k0 + tcol;
            *(unsigned*)&WsH[n][tcol] = *(const unsigned*)&Whi[gw];
            *(unsigned*)&WsL[n][tcol] = *(const unsigned*)&Wlo[gw];
        }
        __syncthreads();
#pragma unroll
        for (int ks = 0; ks < 2; ++ks) {
            const int kk = ks*16 + (lane&3)*2;
            unsigned ah[2][4], al[2][4], bh[4][2], bl[4][2];
#pragma unroll
            for (int mf=0; mf<2; ++mf) {
                int r = wm*32 + mf*16 + (lane>>2);
                ah[mf][0]=*(const unsigned*)&AsH[r][kk];
                ah[mf][1]=*(const unsigned*)&AsH[r+8][kk];
                ah[mf][2]=*(const unsigned*)&AsH[r][kk+8];
                ah[mf][3]=*(const unsigned*)&AsH[r+8][kk+8];
                al[mf][0]=*(const unsigned*)&AsL[r][kk];
                al[mf][1]=*(const unsigned*)&AsL[r+8][kk];
                al[mf][2]=*(const unsigned*)&AsL[r][kk+8];
                al[mf][3]=*(const unsigned*)&AsL[r+8][kk+8];
            }
#pragma unroll
            for (int nf=0; nf<4; ++nf) {
                int n = wn*32 + nf*8 + (lane>>2);
                bh[nf][0]=*(const unsigned*)&WsH[n][kk];
                bh[nf][1]=*(const unsigned*)&WsH[n][kk+8];
                bl[nf][0]=*(const unsigned*)&WsL[n][kk];
                bl[nf][1]=*(const unsigned*)&WsL[n][kk+8];
            }
#pragma unroll
            for (int mf=0; mf<2; ++mf)
#pragma unroll
                for (int nf=0; nf<4; ++nf) {
                    mma16816(acc[mf][nf], ah[mf], bh[nf]);
                    mma16816(acc[mf][nf], ah[mf], bl[nf]);
                    mma16816(acc[mf][nf], al[mf], bh[nf]);
                }
        }
        __syncthreads();
    }

#pragma unroll
    for (int mf=0; mf<2; ++mf)
#pragma unroll
        for (int nf=0; nf<4; ++nf) {
            int r = bm + wm*32 + mf*16 + (lane>>2);
            int c = bn + wn*32 + nf*8 + (lane&3)*2;
            float b0 = bias[c], b1 = bias[c+1];
            float v00 = acc[mf][nf][0]+b0, v01 = acc[mf][nf][1]+b1;
            float v10 = acc[mf][nf][2]+b0, v11 = acc[mf][nf][3]+b1;
            if (relu) {
                v00=fmaxf(v00,0.f); v01=fmaxf(v01,0.f);
                v10=fmaxf(v10,0.f); v11=fmaxf(v11,0.f);
            }
            if (outF) {
                outF[(size_t)r*N + c]   = v00; outF[(size_t)r*N + c+1]   = v01;
                outF[(size_t)(r+8)*N+c] = v10; outF[(size_t)(r+8)*N+c+1] = v11;
            }
            if (outHi) {
                __nv_bfloat16 h0,l0,h1,l1;
                splitf(v00,h0,l0); splitf(v01,h1,l1);
                __nv_bfloat162 hh; hh.x=h0; hh.y=h1;
                __nv_bfloat162 ll; ll.x=l0; ll.y=l1;
                *(__nv_bfloat162*)&outHi[(size_t)r*N + c] = hh;
                *(__nv_bfloat162*)&outLo[(size_t)r*N + c] = ll;
                splitf(v10,h0,l0); splitf(v11,h1,l1);
                hh.x=h0; hh.y=h1; ll.x=l0; ll.y=l1;
                *(__nv_bfloat162*)&outHi[(size_t)(r+8)*N + c] = hh;
                *(__nv_bfloat162*)&outLo[(size_t)(r+8)*N + c] = ll;
            }
        }
}

// ---- SA3 feature build ----
__global__ void feats3_split_kernel(const float* __restrict__ x2, const float* __restrict__ pos2,
                                    __nv_bfloat16* __restrict__ hi, __nv_bfloat16* __restrict__ lo)
{
    int row = blockIdx.x*2 + (threadIdx.x>>7);
    int c0 = threadIdx.x & 127;
    for (int c = c0; c < 288; c += 128) {
        float v = (c < 256) ? x2[(size_t)row*256 + c]
                : (c < 259) ? pos2[row*3 + c - 256] : 0.f;
        splitf(v, hi[(size_t)row*288 + c], lo[(size_t)row*288 + c]);
    }
}

__global__ void pool256_kernel(const float* __restrict__ g, float* __restrict__ gfeat)
{
    int b = blockIdx.y, f = blockIdx.x*256 + threadIdx.x;
    float m = -FLT_MAX;
    for (int r = 0; r < M2C; ++r)
        m = fmaxf(m, g[(size_t)(b*M2C+r)*1024 + f]);
    gfeat[b*1024+f]=m;
}

__global__ void head_kernel(const float* __restrict__ gfeat,
                            const float* __restrict__ Wh1, const float* __restrict__ bh1,
                            const float* __restrict__ Wh2, const float* __restrict__ bh2,
                            const float* __restrict__ Wh3, const float* __restrict__ bh3,
                            float* __restrict__ out)
{
    __shared__ float gf[1024], h1[512], h2[256], lg[10];
    const int b=blockIdx.x, tid=threadIdx.x;
    for (int i = tid; i < 1024; i += 256) gf[i]=gfeat[b*1024+i];
    __syncthreads();
    for (int n = tid; n < 512; n += 256) {
        float s = bh1[n];
        for (int k = 0; k < 1024; ++k) s += gf[k]*Wh1[(size_t)k*512+n];
        h1[n]=fmaxf(s,0.f);
    }
    __syncthreads();
    { float s = bh2[tid];
      for (int k = 0; k < 512; ++k) s += h1[k]*Wh2[(size_t)k*256+tid];
      h2[tid]=fmaxf(s,0.f); }
    __syncthreads();
    if (tid < 10) {
        float s = bh3[tid];
        for (int k = 0; k < 256; ++k) s += h2[k]*Wh3[k*10+tid];
        lg[tid]=s;
    }
    __syncthreads();
    if (tid == 0) {
        float m=lg[0];
        for (int j=1;j<10;++j) m=fmaxf(m,lg[j]);
        float se=0.f;
        for (int j=0;j<10;++j) se+=expf(lg[j]-m);
        float l=logf(se);
        for (int j=0;j<10;++j) out[b*10+j]=lg[j]-m-l;
    }
}

extern "C" void kernel_launch(void* const* d_in, const int* in_sizes, int n_in,
                              void* d_out, int out_size)
{
    const float* pos=(const float*)d_in[0];
    const float *W1a=(const float*)d_in[1],  *b1a=(const float*)d_in[2];
    const float *W1b=(const float*)d_in[3],  *b1b=(const float*)d_in[4];
    const float *W1c=(const float*)d_in[5],  *b1c=(const float*)d_in[6];
    const float *W2a=(const float*)d_in[7],  *b2a=(const float*)d_in[8];
    const float *W2b=(const float*)d_in[9],  *b2b=(const float*)d_in[10];
    const float *W2c=(const float*)d_in[11], *b2c=(const float*)d_in[12];
    const float *W3a=(const float*)d_in[13], *b3a=(const float*)d_in[14];
    const float *W3b=(const float*)d_in[15], *b3b=(const float*)d_in[16];
    const float *W3c=(const float*)d_in[17], *b3c=(const float*)d_in[18];
    const float *Wh1=(const float*)d_in[19], *bh1=(const float*)d_in[20];
    const float *Wh2=(const float*)d_in[21], *bh2=(const float*)d_in[22];
    const float *Wh3=(const float*)d_in[23], *bh3=(const float*)d_in[24];

    float *curv,*pos1,*curv1,*pos2,*x1,*x2,*gfeat,*fF,*bA;
    int *nidx1,*cnt1,*nidx2,*cnt2;
    __nv_bfloat16 *w1bh,*w1bl,*w1ch,*w1cl,*w2bh,*w2bl,*w2ch,*w2cl;
    __nv_bfloat16 *w3ah,*w3al,*w3bh,*w3bl,*w3ch,*w3cl;
    __nv_bfloat16 *pAh,*pAl,*pBh,*pBl,*pCh,*pCl;
    cudaGetSymbolAddress((void**)&curv, g_curv);
    cudaGetSymbolAddress((void**)&pos1, g_pos1);
    cudaGetSymbolAddress((void**)&curv1,g_curv1);
    cudaGetSymbolAddress((void**)&pos2, g_pos2);
    cudaGetSymbolAddress((void**)&nidx1,g_nidx1);
    cudaGetSymbolAddress((void**)&cnt1, g_cnt1);
    cudaGetSymbolAddress((void**)&nidx2,g_nidx2);
    cudaGetSymbolAddress((void**)&cnt2, g_cnt2);
    cudaGetSymbolAddress((void**)&x1,   g_x1);
    cudaGetSymbolAddress((void**)&x2,   g_x2);
    cudaGetSymbolAddress((void**)&gfeat,g_gfeat);
    cudaGetSymbolAddress((void**)&fF,   g_featF);
    cudaGetSymbolAddress((void**)&bA,   g_bufA);
    cudaGetSymbolAddress((void**)&w1bh, g_w1bh); cudaGetSymbolAddress((void**)&w1bl, g_w1bl);
    cudaGetSymbolAddress((void**)&w1ch, g_w1ch); cudaGetSymbolAddress((void**)&w1cl, g_w1cl);
    cudaGetSymbolAddress((void**)&w2bh, g_w2bh); cudaGetSymbolAddress((void**)&w2bl, g_w2bl);
    cudaGetSymbolAddress((void**)&w2ch, g_w2ch); cudaGetSymbolAddress((void**)&w2cl, g_w2cl);
    cudaGetSymbolAddress((void**)&w3ah, g_w3ah); cudaGetSymbolAddress((void**)&w3al, g_w3al);
    cudaGetSymbolAddress((void**)&w3bh, g_w3bh); cudaGetSymbolAddress((void**)&w3bl, g_w3bl);
    cudaGetSymbolAddress((void**)&w3ch, g_w3ch); cudaGetSymbolAddress((void**)&w3cl, g_w3cl);
    cudaGetSymbolAddress((void**)&pAh,  g_pAh);  cudaGetSymbolAddress((void**)&pAl,  g_pAl);
    cudaGetSymbolAddress((void**)&pBh,  g_pBh);  cudaGetSymbolAddress((void**)&pBl,  g_pBl);
    cudaGetSymbolAddress((void**)&pCh,  g_pCh);  cudaGetSymbolAddress((void**)&pCl,  g_pCl);

    cudaFuncSetAttribute(sa1_fused_kernel, cudaFuncAttributeMaxDynamicSharedMemorySize, 98304);
    cudaFuncSetAttribute(sa2_fused_kernel, cudaFuncAttributeMaxDynamicSharedMemorySize, 144896);

    cudaStream_t s2; cudaStreamCreateWithFlags(&s2, cudaStreamNonBlocking);
    cudaEvent_t e0, eW, e1, e2;
    cudaEventCreateWithFlags(&e0, cudaEventDisableTiming);
    cudaEventCreateWithFlags(&eW, cudaEventDisableTiming);
    cudaEventCreateWithFlags(&e1, cudaEventDisableTiming);
    cudaEventCreateWithFlags(&e2, cudaEventDisableTiming);

    // weight preps on s2 (R8 structure)
    cudaEventRecord(e0, 0);
    cudaStreamWaitEvent(s2, e0, 0);
    wprep_kernel<<<16, 256, 0, s2>>>(W1b, w1bh, w1bl, 64, 64);
    wprep_kernel<<<32, 256, 0, s2>>>(W1c, w1ch, w1cl, 64, 128);
    wprep_kernel<<<64, 256, 0, s2>>>(W2b, w2bh, w2bl, 128, 128);
    wprep_kernel<<<128,256, 0, s2>>>(W2c, w2ch, w2cl, 128, 256);
    wprep_pad_kernel<<<288, 256, 0, s2>>>(W3a, w3ah, w3al, 259, 256, 288);
    wprep_kernel<<<512, 256, 0, s2>>>(W3b, w3bh, w3bl, 256, 512);
    wprep_kernel<<<2048,256, 0, s2>>>(W3c, w3ch, w3cl, 512, 1024);
    cudaEventRecord(eW, s2);

    // curvature (split-scan, 256 thr) + FPS1 (fused gather -> pos1/curv1)
    curvature_kernel<<<BATCH*(NPT/128), 256>>>(pos, curv);
    fps_kernel<NPT,M1C><<<BATCH, 256>>>(pos, curv, pos1, curv1);
    cudaEventRecord(e1, 0);

    // branch B on s2: FPS2 + group2
    cudaStreamWaitEvent(s2, e1, 0);
    fps_kernel<M1C,M2C><<<BATCH, 256, 0, s2>>>(pos1, curv1, pos2, (float*)0);
    group_kernel<M1C,512,4><<<dim3(M2C/4, BATCH), 128, 0, s2>>>(pos1, pos2, nidx2, cnt2, M2C, 0.16f);
    cudaEventRecord(e2, s2);

    // branch A on main: group1 + SA1 (writes x1 AND y1; 2 blocks/SM)
    group_kernel<NPT,128,8><<<dim3(M1C/8, BATCH), 256>>>(pos, pos1, nidx1, cnt1, M1C, 0.04f);
    cudaStreamWaitEvent(0, eW, 0);
    sa1_fused_kernel<<<304, 256, 98304>>>(pos, pos1, nidx1, cnt1,
        W1a, b1a, w1bh, w1bl, b1b, w1ch, w1cl, b1c, W2a, b2a, x1, fF);

    // join, SA2
    cudaStreamWaitEvent(0, e2, 0);
    sa2_fused_kernel<<<BATCH*M2C/2, 256, 144896>>>(fF, pos1, pos2, nidx2, cnt2,
        W2a, w2bh, w2bl, b2b, w2ch, w2cl, b2c, x2);

    // SA3 on tensor cores
    feats3_split_kernel<<<BATCH*M2C/2, 256>>>(x2, pos2, pAh, pAl);
    mma_gemm_kernel<<<dim3(4, 16), 256>>>(pAh, pAl, w3ah, w3al, b3a,
                                          (float*)0, pBh, pBl, 256, 288, 1);
    mma_gemm_kernel<<<dim3(8, 16), 256>>>(pBh, pBl, w3bh, w3bl, b3b,
                                          (float*)0, pCh, pCl, 512, 256, 1);
    mma_gemm_kernel<<<dim3(16, 16), 256>>>(pCh, pCl, w3ch, w3cl, b3c,
                                           bA, (__nv_bfloat16*)0, (__nv_bfloat16*)0, 1024, 512, 0);
    pool256_kernel<<<dim3(4, BATCH), 256>>>(bA, gfeat);

    // head
    head_kernel<<<BATCH, 256>>>(gfeat, Wh1, bh1, Wh2, bh2, Wh3, bh3, (float*)d_out);
}